// round 14
// baseline (speedup 1.0000x reference)
#include <cuda_runtime.h>
#include <cuda_fp16.h>
#include <cstdint>
#include <math.h>

// Problem constants
#define B_   4
#define L_   2048
#define DM   1024
#define H_   16
#define HD   64
#define M_   (B_ * L_)       // 8192 rows
#define EPSC 1e-6f
#define CH   64              // scan chunk length
#define NCH  (L_ / CH)       // 32 chunks

// GEMM constants (validated shape): CTA 128x128, warp tile 32x64, BK=64
#define KC        64
#define KCHUNKS   (DM / KC)           // 16
#define TILE_B    16384               // 128-row x 128-byte tile
#define STG_B     (2 * TILE_B)        // 32 KB
#define NSTG      3
#define SMEM_GEMM (NSTG * STG_B)      // 96 KB, occ 2

// chunk_out dynamic smem layout (bytes)
#define CO_Q    0
#define CO_V    8192
#define CO_K    16384
#define CO_SP   24576
#define CO_NUM  32768                       // float [64][72]
#define CO_ZW   (CO_NUM + 64 * 72 * 4)      // 51200: float [64][64]
#define CO_RED  (CO_ZW + 64 * 64 * 4)       // 67584: float [2][16][68]
#define CO_PART (CO_RED + 2 * 16 * 68 * 4)  // 76288: float [4][64]
#define CO_SMEM (CO_PART + 4 * 64 * 4)      // 77312

// ---------------------------------------------------------------------------
// Scratch (allocation-free rule: __device__ globals)
// ---------------------------------------------------------------------------
__device__ float  g_S[(size_t)B_ * H_ * NCH * HD * HD]; // chunk S sums -> prefix
__device__ float  g_Z[(size_t)B_ * H_ * NCH * HD];      // chunk Z sums -> prefix
__device__ __half g_A16[(size_t)3 * M_ * DM];           // fp16 A slabs (in / attn out)
__device__ __half g_W16[(size_t)4 * DM * DM];           // [N,K] fp16, 4 slabs
__device__ __half g_Q16[(size_t)M_ * DM];
__device__ __half g_K16[(size_t)M_ * DM];
__device__ __half g_V16[(size_t)M_ * DM];

// ---------------------------------------------------------------------------
// Static stream/event set for graph-captured fork/join overlap.
// Created at program load (before the harness's memory baseline); these are
// not device-memory allocation APIs. Sequential fallback if creation fails.
// ---------------------------------------------------------------------------
struct OverlapRes {
    cudaStream_t s2 = nullptr;
    cudaEvent_t evRoot = nullptr, evConvA = nullptr, evKV = nullptr,
                evQ = nullptr, evScan = nullptr;
    bool ok = false;
    OverlapRes() {
        if (cudaStreamCreateWithFlags(&s2, cudaStreamNonBlocking) != cudaSuccess) return;
        if (cudaEventCreateWithFlags(&evRoot,  cudaEventDisableTiming) != cudaSuccess) return;
        if (cudaEventCreateWithFlags(&evConvA, cudaEventDisableTiming) != cudaSuccess) return;
        if (cudaEventCreateWithFlags(&evKV,    cudaEventDisableTiming) != cudaSuccess) return;
        if (cudaEventCreateWithFlags(&evQ,     cudaEventDisableTiming) != cudaSuccess) return;
        if (cudaEventCreateWithFlags(&evScan,  cudaEventDisableTiming) != cudaSuccess) return;
        ok = true;
    }
};
static OverlapRes g_ovl;

// ---------------------------------------------------------------------------
// PTX helpers (base-target sm_103-safe)
// ---------------------------------------------------------------------------
__device__ __forceinline__ uint32_t smem_u32(const void* p) {
    uint32_t a;
    asm("{ .reg .u64 t; cvta.to.shared.u64 t, %1; cvt.u32.u64 %0, t; }" : "=r"(a) : "l"(p));
    return a;
}
__device__ __forceinline__ void cp16(uint32_t saddr, const void* g) {
    asm volatile("cp.async.cg.shared.global [%0], [%1], 16;\n" :: "r"(saddr), "l"(g));
}
#define CP_COMMIT() asm volatile("cp.async.commit_group;\n")
#define CP_WAIT1()  asm volatile("cp.async.wait_group 1;\n")

__device__ __forceinline__ void ldsm4(uint32_t* r, uint32_t addr) {
    asm volatile("ldmatrix.sync.aligned.m8n8.x4.shared.b16 {%0,%1,%2,%3}, [%4];"
                 : "=r"(r[0]), "=r"(r[1]), "=r"(r[2]), "=r"(r[3]) : "r"(addr));
}
__device__ __forceinline__ void ldsm4t(uint32_t* r, uint32_t addr) {
    asm volatile("ldmatrix.sync.aligned.m8n8.x4.trans.shared.b16 {%0,%1,%2,%3}, [%4];"
                 : "=r"(r[0]), "=r"(r[1]), "=r"(r[2]), "=r"(r[3]) : "r"(addr));
}
__device__ __forceinline__ void mma16816(float* d, const uint32_t* a,
                                         uint32_t b0, uint32_t b1) {
    asm volatile(
        "mma.sync.aligned.m16n8k16.row.col.f32.f16.f16.f32 "
        "{%0,%1,%2,%3}, {%4,%5,%6,%7}, {%8,%9}, {%0,%1,%2,%3};"
        : "+f"(d[0]), "+f"(d[1]), "+f"(d[2]), "+f"(d[3])
        : "r"(a[0]), "r"(a[1]), "r"(a[2]), "r"(a[3]), "r"(b0), "r"(b1));
}
__device__ __forceinline__ uint32_t pack2(float lo, float hi) {
    uint32_t d;
    asm("cvt.rn.f16x2.f32 %0, %1, %2;" : "=r"(d) : "f"(hi), "f"(lo));
    return d;
}

// SW128 swizzle within a tile of 128-byte rows
__device__ __forceinline__ uint32_t swaddr(uint32_t tilebase, int row, int cbyte) {
    uint32_t off = ((uint32_t)(row >> 3) << 10) + ((uint32_t)(row & 7) << 7)
                 + (uint32_t)cbyte;
    return tilebase + (off ^ ((off >> 3) & 0x70u));
}
// Fragment source address: row-major operand [r][k] (16-row x 16-col block)
__device__ __forceinline__ uint32_t naddr(uint32_t tile, int r0, int kb, int q, int lr) {
    return swaddr(tile, r0 + (q & 1) * 8 + lr, kb + (q >> 1) * 16);
}
// Trans fragment: smem holds T[j][col]; want op[m_or_n=col][k=j]
__device__ __forceinline__ uint32_t taddr(uint32_t tile, int j0, int col0, int q, int lr) {
    return swaddr(tile, j0 + (q >> 1) * 8 + lr, (col0 + (q & 1) * 8) * 2);
}

// ---------------------------------------------------------------------------
// Converters (batched)
// ---------------------------------------------------------------------------
__global__ __launch_bounds__(256)
void conv_a_all(const float* __restrict__ X0, const float* __restrict__ X1,
                const float* __restrict__ X2, __half* __restrict__ Y)
{
    const int slab = blockIdx.y;
    const float* X = (slab == 0) ? X0 : (slab == 1) ? X1 : X2;
    const size_t i = ((size_t)blockIdx.x * 256 + threadIdx.x) * 4;
    float4 v = *(const float4*)(X + i);
    uint2 u;
    u.x = pack2(v.x, v.y);
    u.y = pack2(v.z, v.w);
    *(uint2*)(Y + (size_t)slab * M_ * DM + i) = u;
}

__global__ __launch_bounds__(256)
void conv_w_all(const float* __restrict__ W0, const float* __restrict__ W1,
                const float* __restrict__ W2, const float* __restrict__ W3,
                __half* __restrict__ Y)
{
    __shared__ float s[32][33];
    const int slab = blockIdx.z;
    const float* W = (slab == 0) ? W0 : (slab == 1) ? W1 : (slab == 2) ? W2 : W3;
    __half* Yo = Y + (size_t)slab * DM * DM;
    const int n0 = blockIdx.x * 32, k0 = blockIdx.y * 32;
    const int tx = threadIdx.x & 31, ty = threadIdx.x >> 5;
    #pragma unroll
    for (int i = 0; i < 4; i++)
        s[ty + i * 8][tx] = W[(size_t)(k0 + ty + i * 8) * DM + n0 + tx];
    __syncthreads();
    #pragma unroll
    for (int i = 0; i < 4; i++) {
        float x = s[tx][ty + i * 8];
        Yo[(size_t)(n0 + ty + i * 8) * DM + k0 + tx] = __float2half_rn(x);
    }
}

// ---------------------------------------------------------------------------
// fp16 tensor GEMM (validated), fp32 or fp16 output. Slab selection by
// pointer offset at the call site (A16/W16 bases pre-offset).
// ---------------------------------------------------------------------------
__device__ __forceinline__ void load_chunk(
    const __half* A16, const __half* B16,
    size_t aRowBase, int n0, int tid, int ch, uint32_t stg)
{
    const int r0 = tid >> 3;
    const int c  = tid & 7;
    const uint32_t kbyte = (uint32_t)ch * (KC * 2);
    #pragma unroll
    for (int i = 0; i < 4; i++) {
        const int r = r0 + 32 * i;
        const uint32_t sw = swaddr(0, r, c * 16);
        cp16(stg + 0 * TILE_B + sw,
             (const char*)A16 + (aRowBase + r) * (DM * 2) + kbyte + c * 16);
        cp16(stg + 1 * TILE_B + sw,
             (const char*)B16 + (size_t)(n0 + r) * (DM * 2) + kbyte + c * 16);
    }
}

__global__ __launch_bounds__(256, 2)
void gemm_tc_kernel(const __half* __restrict__ A16,
                    const __half* __restrict__ W16,
                    const float* __restrict__ b0, const float* __restrict__ b1,
                    const float* __restrict__ b2,
                    void* C0v, void* C1v, void* C2v,
                    int actmask, int outhalf)
{
    extern __shared__ char smem[];
    const uint32_t sbase = smem_u32(smem);

    const int slab = blockIdx.z;
    const __half* B16 = W16 + (size_t)slab * DM * DM;
    const float* bias = (slab == 0) ? b0 : (slab == 1) ? b1 : b2;
    void* Cv = (slab == 0) ? C0v : (slab == 1) ? C1v : C2v;
    const int act = (actmask >> slab) & 1;

    const int tid  = threadIdx.x;
    const int wid  = tid >> 5, lane = tid & 31;
    const int wr   = wid & 3;
    const int wc   = wid >> 2;
    const int m0 = blockIdx.y * 128;
    const size_t aRowBase = (size_t)slab * M_ + m0;
    const int n0 = blockIdx.x * 128;

    const int q   = lane >> 3;
    const int lr  = lane & 7;
    const int kQ  = (q >> 1) * 16;

    float acc[2][8][4];
    #pragma unroll
    for (int mt = 0; mt < 2; mt++)
        #pragma unroll
        for (int nt = 0; nt < 8; nt++)
            #pragma unroll
            for (int e = 0; e < 4; e++) acc[mt][nt][e] = 0.f;

    load_chunk(A16, B16, aRowBase, n0, tid, 0, sbase + 0 * STG_B);
    CP_COMMIT();
    load_chunk(A16, B16, aRowBase, n0, tid, 1, sbase + 1 * STG_B);
    CP_COMMIT();

    for (int chk = 0; chk < KCHUNKS; chk++) {
        CP_WAIT1();
        __syncthreads();

        if (chk + 2 < KCHUNKS)
            load_chunk(A16, B16, aRowBase, n0, tid, chk + 2,
                       sbase + ((chk + 2) % NSTG) * STG_B);
        CP_COMMIT();

        const uint32_t stg = sbase + (chk % NSTG) * STG_B;
        const uint32_t tA  = stg + 0 * TILE_B;
        const uint32_t tB  = stg + 1 * TILE_B;

        #pragma unroll
        for (int k16 = 0; k16 < 4; k16++) {
            const int kb = k16 * 32 + kQ;
            uint32_t Af[2][4];
            #pragma unroll
            for (int mt = 0; mt < 2; mt++)
                ldsm4(Af[mt], swaddr(tA, wr * 32 + mt * 16 + (q & 1) * 8 + lr, kb));
            #pragma unroll
            for (int g = 0; g < 4; g++) {
                uint32_t Bf[4];
                ldsm4(Bf, swaddr(tB, wc * 64 + g * 16 + (q & 1) * 8 + lr, kb));
                #pragma unroll
                for (int s = 0; s < 2; s++) {
                    const int nt = g * 2 + s;
                    #pragma unroll
                    for (int mt = 0; mt < 2; mt++)
                        mma16816(acc[mt][nt], Af[mt], Bf[s], Bf[s + 2]);
                }
            }
        }
    }

    // epilogue
    #pragma unroll
    for (int mt = 0; mt < 2; mt++) {
        const int row = m0 + wr * 32 + mt * 16 + (lane >> 2);
        #pragma unroll
        for (int nt = 0; nt < 8; nt++) {
            const int col = n0 + wc * 64 + nt * 8 + 2 * (lane & 3);
            const float bb0 = bias[col], bb1 = bias[col + 1];
            float v0 = acc[mt][nt][0] + bb0;
            float v1 = acc[mt][nt][1] + bb1;
            float v2 = acc[mt][nt][2] + bb0;
            float v3 = acc[mt][nt][3] + bb1;
            if (act) {
                v0 = (v0 > 0.f) ? (v0 + 1.f) : expf(v0);
                v1 = (v1 > 0.f) ? (v1 + 1.f) : expf(v1);
                v2 = (v2 > 0.f) ? (v2 + 1.f) : expf(v2);
                v3 = (v3 > 0.f) ? (v3 + 1.f) : expf(v3);
            }
            if (outhalf) {
                __half* Ch = (__half*)Cv;
                *(uint32_t*)(Ch + (size_t)row * DM + col)       = pack2(v0, v1);
                *(uint32_t*)(Ch + (size_t)(row + 8) * DM + col) = pack2(v2, v3);
            } else {
                float* C = (float*)Cv;
                *(float2*)(C + (size_t)row * DM + col)       = make_float2(v0, v1);
                *(float2*)(C + (size_t)(row + 8) * DM + col) = make_float2(v2, v3);
            }
        }
    }
}

// ---------------------------------------------------------------------------
// Scan kernel A: per-chunk S[c][a] = sum_j V[j][c] K[j][a] and Z[a] (tensor)
// ---------------------------------------------------------------------------
__global__ __launch_bounds__(128, 4)
void attn_chunk_sums(const __half* __restrict__ K16,
                     const __half* __restrict__ V16,
                     float* __restrict__ S,
                     float* __restrict__ Z)
{
    __shared__ __align__(128) __half sK[64 * 64];
    __shared__ __align__(128) __half sV[64 * 64];

    const int ch = blockIdx.x, bh = blockIdx.y;
    const int b = bh >> 4, h = bh & 15;
    const size_t base = ((size_t)(b * L_ + ch * CH)) * DM + h * HD;
    const int tid = threadIdx.x;
    const uint32_t uK = smem_u32(sK), uV = smem_u32(sV);

    for (int f = tid; f < 512; f += 128) {
        const int r = f >> 3, c = f & 7;
        *(uint4*)((char*)sK + swaddr(0, r, c * 16)) =
            *(const uint4*)(K16 + base + (size_t)r * DM + c * 8);
        *(uint4*)((char*)sV + swaddr(0, r, c * 16)) =
            *(const uint4*)(V16 + base + (size_t)r * DM + c * 8);
    }
    __syncthreads();

    const int wid = tid >> 5, lane = tid & 31;
    const int q = lane >> 3, lr = lane & 7;
    const int c0 = (wid >> 1) * 32, a0 = (wid & 1) * 32;

    float sacc[2][4][4];
    #pragma unroll
    for (int mt = 0; mt < 2; mt++)
        #pragma unroll
        for (int nt = 0; nt < 4; nt++)
            #pragma unroll
            for (int e = 0; e < 4; e++) sacc[mt][nt][e] = 0.f;

    #pragma unroll
    for (int jk = 0; jk < 4; jk++) {
        uint32_t Af[2][4];
        #pragma unroll
        for (int mt = 0; mt < 2; mt++)
            ldsm4t(Af[mt], taddr(uV, jk * 16, c0 + mt * 16, q, lr));
        #pragma unroll
        for (int nb = 0; nb < 2; nb++) {
            uint32_t Bf[4];
            ldsm4t(Bf, taddr(uK, jk * 16, a0 + nb * 16, q, lr));
            #pragma unroll
            for (int s = 0; s < 2; s++)
                #pragma unroll
                for (int mt = 0; mt < 2; mt++)
                    mma16816(sacc[mt][nb * 2 + s], Af[mt], Bf[s], Bf[s + 2]);
        }
    }

    float* sout = S + ((size_t)bh * NCH + ch) * (HD * HD);
    #pragma unroll
    for (int mt = 0; mt < 2; mt++)
        #pragma unroll
        for (int nt = 0; nt < 4; nt++) {
            const int c = c0 + mt * 16 + (lane >> 2);
            const int a = a0 + nt * 8 + 2 * (lane & 3);
            *(float2*)(sout + (size_t)c * HD + a) =
                make_float2(sacc[mt][nt][0], sacc[mt][nt][1]);
            *(float2*)(sout + (size_t)(c + 8) * HD + a) =
                make_float2(sacc[mt][nt][2], sacc[mt][nt][3]);
        }

    if (tid < 64) {
        float s0 = 0.f, s1 = 0.f;
        #pragma unroll 8
        for (int j = 0; j < 64; j += 2) {
            s0 += __half2float(*(const __half*)((const char*)sK + swaddr(0, j, tid * 2)));
            s1 += __half2float(*(const __half*)((const char*)sK + swaddr(0, j + 1, tid * 2)));
        }
        Z[((size_t)bh * NCH + ch) * HD + tid] = s0 + s1;
    }
}

// ---------------------------------------------------------------------------
// Scan kernel B: exclusive prefix over chunks.
// ---------------------------------------------------------------------------
__global__ __launch_bounds__(512, 1)
void attn_prefix(float* __restrict__ S, float* __restrict__ Z)
{
    const int bh = blockIdx.x;
    const int tid = threadIdx.x;
    const size_t sb = (size_t)bh * NCH * (HD * HD);

    float run[8];
    #pragma unroll
    for (int u = 0; u < 8; u++) run[u] = 0.f;

    for (int ch = 0; ch < NCH; ch++) {
        #pragma unroll
        for (int u = 0; u < 8; u++) {
            const size_t idx = sb + (size_t)ch * (HD * HD) + tid + u * 512;
            float t = S[idx];
            S[idx] = run[u];
            run[u] += t;
        }
    }

    if (tid < 64) {
        const size_t zb = (size_t)bh * NCH * HD;
        float rz = 0.f;
        for (int ch = 0; ch < NCH; ch++) {
            float t = Z[zb + (size_t)ch * HD + tid];
            Z[zb + (size_t)ch * HD + tid] = rz;
            rz += t;
        }
    }
}

// ---------------------------------------------------------------------------
// Scan kernel C: per-chunk outputs, tensorized (validated R13).
// ---------------------------------------------------------------------------
__global__ __launch_bounds__(256, 2)
void attn_chunk_out(const __half* __restrict__ Q16,
                    const __half* __restrict__ K16,
                    const __half* __restrict__ V16,
                    const float* __restrict__ Sp,
                    const float* __restrict__ Zp,
                    __half* __restrict__ O16)
{
    extern __shared__ char cosm[];
    const uint32_t ub = smem_u32(cosm);

    const int ch = blockIdx.x, bh = blockIdx.y;
    const int b = bh >> 4, h = bh & 15;
    const size_t base = ((size_t)(b * L_ + ch * CH)) * DM + h * HD;
    const int tid = threadIdx.x;

    for (int f = tid; f < 512; f += 256) {
        const int r = f >> 3, c = f & 7;
        const uint32_t sw = swaddr(0, r, c * 16);
        *(uint4*)(cosm + CO_Q + sw) = *(const uint4*)(Q16 + base + (size_t)r * DM + c * 8);
        *(uint4*)(cosm + CO_V + sw) = *(const uint4*)(V16 + base + (size_t)r * DM + c * 8);
        *(uint4*)(cosm + CO_K + sw) = *(const uint4*)(K16 + base + (size_t)r * DM + c * 8);
    }
    {
        const float* sp = Sp + ((size_t)bh * NCH + ch) * (HD * HD);
        #pragma unroll
        for (int it = 0; it < 4; it++) {
            const int e = (tid + it * 256) * 4;
            const int c = e >> 6, a = e & 63;
            float4 v = *(const float4*)(sp + (size_t)c * HD + a);
            uint2 u;
            u.x = pack2(v.x, v.y);
            u.y = pack2(v.z, v.w);
            *(uint2*)(cosm + CO_SP + swaddr(0, c, a * 2)) = u;
        }
    }
    __syncthreads();

    const int wid = tid >> 5, lane = tid & 31;
    const int q = lane >> 3, lr = lane & 7;
    const int wr = wid & 3, wc = wid >> 2;
    const int i0 = wr * 16, j0 = wc * 32;
    const bool active = (j0 <= i0 + 15);

    const uint32_t uQ = ub + CO_Q, uV = ub + CO_V, uK = ub + CO_K, uSp = ub + CO_SP;

    float numacc[8][4];
    #pragma unroll
    for (int nt = 0; nt < 8; nt++)
        #pragma unroll
        for (int e = 0; e < 4; e++) numacc[nt][e] = 0.f;

    if (active) {
        float gacc[4][4];
        #pragma unroll
        for (int nt = 0; nt < 4; nt++)
            #pragma unroll
            for (int e = 0; e < 4; e++) gacc[nt][e] = 0.f;

        #pragma unroll
        for (int kc = 0; kc < 4; kc++) {
            const int kb = kc * 32 + (q >> 1) * 16;
            uint32_t Aq[4];
            ldsm4(Aq, naddr(uQ, i0, kc * 32, q, lr));
            #pragma unroll
            for (int g = 0; g < 2; g++) {
                uint32_t Bv[4];
                ldsm4(Bv, swaddr(uV, j0 + g * 16 + (q & 1) * 8 + lr, kb));
                mma16816(gacc[g * 2 + 0], Aq, Bv[0], Bv[2]);
                mma16816(gacc[g * 2 + 1], Aq, Bv[1], Bv[3]);
            }
            if (wc == 0) {
                #pragma unroll
                for (int nb = 0; nb < 4; nb++) {
                    uint32_t Bs[4];
                    ldsm4t(Bs, taddr(uSp, kc * 16, nb * 16, q, lr));
                    mma16816(numacc[nb * 2 + 0], Aq, Bs[0], Bs[2]);
                    mma16816(numacc[nb * 2 + 1], Aq, Bs[1], Bs[3]);
                }
            }
        }

        #pragma unroll
        for (int nt = 0; nt < 4; nt++) {
            const int jb = j0 + nt * 8 + 2 * (lane & 3);
            const int ib = i0 + (lane >> 2);
            if (jb     > ib)     gacc[nt][0] = 0.f;
            if (jb + 1 > ib)     gacc[nt][1] = 0.f;
            if (jb     > ib + 8) gacc[nt][2] = 0.f;
            if (jb + 1 > ib + 8) gacc[nt][3] = 0.f;
        }
        uint32_t aG[2][4];
        #pragma unroll
        for (int t = 0; t < 2; t++) {
            aG[t][0] = pack2(gacc[2 * t][0],     gacc[2 * t][1]);
            aG[t][1] = pack2(gacc[2 * t][2],     gacc[2 * t][3]);
            aG[t][2] = pack2(gacc[2 * t + 1][0], gacc[2 * t + 1][1]);
            aG[t][3] = pack2(gacc[2 * t + 1][2], gacc[2 * t + 1][3]);
        }
        #pragma unroll
        for (int t = 0; t < 2; t++)
            #pragma unroll
            for (int nb = 0; nb < 4; nb++) {
                uint32_t Bk[4];
                ldsm4t(Bk, taddr(uK, j0 + t * 16, nb * 16, q, lr));
                mma16816(numacc[nb * 2 + 0], aG[t], Bk[0], Bk[2]);
                mma16816(numacc[nb * 2 + 1], aG[t], Bk[1], Bk[3]);
            }
    }

    if (wc == 1 && wr >= 2) {
        float* red = (float*)(cosm + CO_RED) + (size_t)(wr - 2) * 16 * 68;
        #pragma unroll
        for (int nt = 0; nt < 8; nt++) {
            const int r = lane >> 2, a = nt * 8 + 2 * (lane & 3);
            *(float2*)(red + r * 68 + a)       = make_float2(numacc[nt][0], numacc[nt][1]);
            *(float2*)(red + (r + 8) * 68 + a) = make_float2(numacc[nt][2], numacc[nt][3]);
        }
    }
    __syncthreads();

    if (wc == 0) {
        if (wr >= 2) {
            const float* red = (const float*)(cosm + CO_RED) + (size_t)(wr - 2) * 16 * 68;
            #pragma unroll
            for (int nt = 0; nt < 8; nt++) {
                const int r = lane >> 2, a = nt * 8 + 2 * (lane & 3);
                float2 p0 = *(const float2*)(red + r * 68 + a);
                float2 p1 = *(const float2*)(red + (r + 8) * 68 + a);
                numacc[nt][0] += p0.x; numacc[nt][1] += p0.y;
                numacc[nt][2] += p1.x; numacc[nt][3] += p1.y;
            }
        }
        float* nm = (float*)(cosm + CO_NUM);
        #pragma unroll
        for (int nt = 0; nt < 8; nt++) {
            const int r = wr * 16 + (lane >> 2), a = nt * 8 + 2 * (lane & 3);
            *(float2*)(nm + r * 72 + a)       = make_float2(numacc[nt][0], numacc[nt][1]);
            *(float2*)(nm + (r + 8) * 72 + a) = make_float2(numacc[nt][2], numacc[nt][3]);
        }
    }
    __syncthreads();

    {
        const int az = tid & 63, seg = tid >> 6;
        float s16 = 0.f;
        #pragma unroll
        for (int i2 = 0; i2 < 16; i2++)
            s16 += __half2float(*(const __half*)(cosm + CO_K + swaddr(0, seg * 16 + i2, az * 2)));
        float* part = (float*)(cosm + CO_PART);
        part[seg * 64 + az] = s16;
        __syncthreads();
        float run = Zp[((size_t)bh * NCH + ch) * HD + az];
        #pragma unroll
        for (int s2 = 0; s2 < 3; s2++)
            if (s2 < seg) run += part[s2 * 64 + az];
        float* zw = (float*)(cosm + CO_ZW);
        #pragma unroll
        for (int i2 = 0; i2 < 16; i2++) {
            run += __half2float(*(const __half*)(cosm + CO_K + swaddr(0, seg * 16 + i2, az * 2)));
            zw[(seg * 16 + i2) * 64 + az] = run;
        }
    }
    __syncthreads();

    {
        const int tx = tid & 15, ty = tid >> 4;
        const float* nm = (const float*)(cosm + CO_NUM);
        const float* zw = (const float*)(cosm + CO_ZW);
        #pragma unroll
        for (int ii = 0; ii < 4; ii++) {
            const int i = ty * 4 + ii;
            float4 n4 = *(const float4*)(nm + i * 72 + tx * 4);
            float4 z4 = *(const float4*)(zw + i * 64 + tx * 4);
            unsigned short o[4];
            #pragma unroll
            for (int aa = 0; aa < 4; aa++) {
                const int a = tx * 4 + aa;
                const float qv = __half2float(
                    *(const __half*)(cosm + CO_Q + swaddr(0, i, a * 2)));
                o[aa] = __half_as_ushort(
                    __float2half_rn((&n4.x)[aa] / (qv * (&z4.x)[aa] + EPSC)));
            }
            uint2 u;
            u.x = (uint32_t)o[0] | ((uint32_t)o[1] << 16);
            u.y = (uint32_t)o[2] | ((uint32_t)o[3] << 16);
            *(uint2*)(O16 + base + (size_t)i * DM + tx * 4) = u;
        }
    }
}

// ---------------------------------------------------------------------------
// kernel_launch — event-forked dual-stream schedule:
//   s0: conv_w → projKV ─evKV─→ projQ ─evQ─┐
//   s2: conv_a ─┘(join)     └→ sums → prefix → (wait evQ) chunk_out ─evScan→
//   s0: (wait evScan) O-proj
// ---------------------------------------------------------------------------
extern "C" void kernel_launch(void* const* d_in, const int* in_sizes, int n_in,
                              void* d_out, int out_size)
{
    const float* queries = (const float*)d_in[0];
    const float* keys    = (const float*)d_in[1];
    const float* values  = (const float*)d_in[2];
    const float* Wq = (const float*)d_in[3];
    const float* bq = (const float*)d_in[4];
    const float* Wk = (const float*)d_in[5];
    const float* bk = (const float*)d_in[6];
    const float* Wv = (const float*)d_in[7];
    const float* bv = (const float*)d_in[8];
    const float* Wo = (const float*)d_in[9];
    const float* bo = (const float*)d_in[10];
    float* out = (float*)d_out;

    float *pS, *pZ;
    __half *pA16, *pW16, *pQ16, *pK16, *pV16;
    cudaGetSymbolAddress((void**)&pS, g_S);
    cudaGetSymbolAddress((void**)&pZ, g_Z);
    cudaGetSymbolAddress((void**)&pA16, g_A16);
    cudaGetSymbolAddress((void**)&pW16, g_W16);
    cudaGetSymbolAddress((void**)&pQ16, g_Q16);
    cudaGetSymbolAddress((void**)&pK16, g_K16);
    cudaGetSymbolAddress((void**)&pV16, g_V16);

    cudaFuncSetAttribute(gemm_tc_kernel,
                         cudaFuncAttributeMaxDynamicSharedMemorySize, SMEM_GEMM);
    cudaFuncSetAttribute(attn_chunk_out,
                         cudaFuncAttributeMaxDynamicSharedMemorySize, CO_SMEM);

    const dim3 chunk_grid(NCH, B_ * H_);

    if (g_ovl.ok) {
        cudaStream_t s0 = 0, s2 = g_ovl.s2;
        // fork s2 from s0
        cudaEventRecord(g_ovl.evRoot, s0);
        cudaStreamWaitEvent(s2, g_ovl.evRoot, 0);

        // conv_w on s0, conv_a on s2 (parallel)
        conv_w_all<<<dim3(DM / 32, DM / 32, 4), 256, 0, s0>>>(Wq, Wk, Wv, Wo, pW16);
        conv_a_all<<<dim3(M_ * DM / 1024, 3), 256, 0, s2>>>(queries, keys, values, pA16);
        cudaEventRecord(g_ovl.evConvA, s2);
        cudaStreamWaitEvent(s0, g_ovl.evConvA, 0);

        // K,V projections (A slabs 1,2; W slabs 1,2): act on K only (z=0)
        gemm_tc_kernel<<<dim3(DM / 128, M_ / 128, 2), 256, SMEM_GEMM, s0>>>(
            pA16 + (size_t)1 * M_ * DM, pW16 + (size_t)1 * DM * DM,
            bk, bv, bv, pK16, pV16, pV16, 0b01, 1);
        cudaEventRecord(g_ovl.evKV, s0);

        // Q projection (A slab 0, W slab 0), act
        gemm_tc_kernel<<<dim3(DM / 128, M_ / 128, 1), 256, SMEM_GEMM, s0>>>(
            pA16, pW16, bq, bq, bq, pQ16, pQ16, pQ16, 0b1, 1);
        cudaEventRecord(g_ovl.evQ, s0);

        // scan head on s2, concurrent with Q projection
        cudaStreamWaitEvent(s2, g_ovl.evKV, 0);
        attn_chunk_sums<<<chunk_grid, 128, 0, s2>>>(pK16, pV16, pS, pZ);
        attn_prefix<<<B_ * H_, 512, 0, s2>>>(pS, pZ);
        cudaStreamWaitEvent(s2, g_ovl.evQ, 0);
        attn_chunk_out<<<chunk_grid, 256, CO_SMEM, s2>>>(pQ16, pK16, pV16, pS, pZ, pA16);
        cudaEventRecord(g_ovl.evScan, s2);

        // join and run output projection on s0
        cudaStreamWaitEvent(s0, g_ovl.evScan, 0);
        gemm_tc_kernel<<<dim3(DM / 128, M_ / 128, 1), 256, SMEM_GEMM, s0>>>(
            pA16, pW16 + (size_t)3 * DM * DM, bo, bo, bo, out, out, out, 0, 0);
    } else {
        // sequential fallback (identical math)
        conv_w_all<<<dim3(DM / 32, DM / 32, 4), 256>>>(Wq, Wk, Wv, Wo, pW16);
        conv_a_all<<<dim3(M_ * DM / 1024, 3), 256>>>(queries, keys, values, pA16);
        gemm_tc_kernel<<<dim3(DM / 128, M_ / 128, 3), 256, SMEM_GEMM>>>(
            pA16, pW16, bq, bk, bv, pQ16, pK16, pV16, 0b011, 1);
        attn_chunk_sums<<<chunk_grid, 128>>>(pK16, pV16, pS, pZ);
        attn_prefix<<<B_ * H_, 512>>>(pS, pZ);
        attn_chunk_out<<<chunk_grid, 256, CO_SMEM>>>(pQ16, pK16, pV16, pS, pZ, pA16);
        gemm_tc_kernel<<<dim3(DM / 128, M_ / 128, 1), 256, SMEM_GEMM>>>(
            pA16, pW16 + (size_t)3 * DM * DM, bo, bo, bo, out, out, out, 0, 0);
    }
}

// round 15
// speedup vs baseline: 1.1274x; 1.1274x over previous
#include <cuda_runtime.h>
#include <cuda_fp16.h>
#include <cstdint>
#include <math.h>

// Problem constants
#define B_   4
#define L_   2048
#define DM   1024
#define H_   16
#define HD   64
#define M_   (B_ * L_)       // 8192 rows
#define EPSC 1e-6f
#define CH   64              // scan chunk length
#define NCH  (L_ / CH)       // 32 chunks

// GEMM constants (validated shape): CTA 128x128, warp tile 32x64, BK=64
#define KC        64
#define KCHUNKS   (DM / KC)           // 16
#define TILE_B    16384               // 128-row x 128-byte tile
#define STG_B     (2 * TILE_B)        // 32 KB
#define NSTG      3
#define SMEM_GEMM (NSTG * STG_B)      // 96 KB, occ 2

// chunk_out dynamic smem layout (bytes)
#define CO_Q    0
#define CO_V    8192
#define CO_K    16384
#define CO_SP   24576
#define CO_NUM  32768                       // float [64][72]
#define CO_ZW   (CO_NUM + 64 * 72 * 4)      // 51200: float [64][64]
#define CO_RED  (CO_ZW + 64 * 64 * 4)       // 67584: float [2][16][68]
#define CO_PART (CO_RED + 2 * 16 * 68 * 4)  // 76288: float [4][64]
#define CO_SMEM (CO_PART + 4 * 64 * 4)      // 77312

// ---------------------------------------------------------------------------
// Scratch (allocation-free rule: __device__ globals)
// ---------------------------------------------------------------------------
__device__ float  g_S[(size_t)B_ * H_ * NCH * HD * HD]; // exclusive-prefix S
__device__ float  g_Z[(size_t)B_ * H_ * NCH * HD];      // exclusive-prefix Z
__device__ __half g_A16[(size_t)3 * M_ * DM];           // fp16 A slabs (in / attn out)
__device__ __half g_W16[(size_t)4 * DM * DM];           // [N,K] fp16, 4 slabs
__device__ __half g_Q16[(size_t)M_ * DM];
__device__ __half g_K16[(size_t)M_ * DM];
__device__ __half g_V16[(size_t)M_ * DM];

// ---------------------------------------------------------------------------
// PTX helpers (base-target sm_103-safe)
// ---------------------------------------------------------------------------
__device__ __forceinline__ uint32_t smem_u32(const void* p) {
    uint32_t a;
    asm("{ .reg .u64 t; cvta.to.shared.u64 t, %1; cvt.u32.u64 %0, t; }" : "=r"(a) : "l"(p));
    return a;
}
__device__ __forceinline__ void cp16(uint32_t saddr, const void* g) {
    asm volatile("cp.async.cg.shared.global [%0], [%1], 16;\n" :: "r"(saddr), "l"(g));
}
#define CP_COMMIT() asm volatile("cp.async.commit_group;\n")
#define CP_WAIT0()  asm volatile("cp.async.wait_group 0;\n")
#define CP_WAIT1()  asm volatile("cp.async.wait_group 1;\n")

__device__ __forceinline__ void ldsm4(uint32_t* r, uint32_t addr) {
    asm volatile("ldmatrix.sync.aligned.m8n8.x4.shared.b16 {%0,%1,%2,%3}, [%4];"
                 : "=r"(r[0]), "=r"(r[1]), "=r"(r[2]), "=r"(r[3]) : "r"(addr));
}
__device__ __forceinline__ void ldsm4t(uint32_t* r, uint32_t addr) {
    asm volatile("ldmatrix.sync.aligned.m8n8.x4.trans.shared.b16 {%0,%1,%2,%3}, [%4];"
                 : "=r"(r[0]), "=r"(r[1]), "=r"(r[2]), "=r"(r[3]) : "r"(addr));
}
__device__ __forceinline__ void mma16816(float* d, const uint32_t* a,
                                         uint32_t b0, uint32_t b1) {
    asm volatile(
        "mma.sync.aligned.m16n8k16.row.col.f32.f16.f16.f32 "
        "{%0,%1,%2,%3}, {%4,%5,%6,%7}, {%8,%9}, {%0,%1,%2,%3};"
        : "+f"(d[0]), "+f"(d[1]), "+f"(d[2]), "+f"(d[3])
        : "r"(a[0]), "r"(a[1]), "r"(a[2]), "r"(a[3]), "r"(b0), "r"(b1));
}
__device__ __forceinline__ uint32_t pack2(float lo, float hi) {
    uint32_t d;
    asm("cvt.rn.f16x2.f32 %0, %1, %2;" : "=r"(d) : "f"(hi), "f"(lo));
    return d;
}

// SW128 swizzle within a tile of 128-byte rows
__device__ __forceinline__ uint32_t swaddr(uint32_t tilebase, int row, int cbyte) {
    uint32_t off = ((uint32_t)(row >> 3) << 10) + ((uint32_t)(row & 7) << 7)
                 + (uint32_t)cbyte;
    return tilebase + (off ^ ((off >> 3) & 0x70u));
}
// Fragment source address: row-major operand [r][k]
__device__ __forceinline__ uint32_t naddr(uint32_t tile, int r0, int kb, int q, int lr) {
    return swaddr(tile, r0 + (q & 1) * 8 + lr, kb + (q >> 1) * 16);
}
// Trans fragment: smem holds T[j][col]; want op[m_or_n=col][k=j]
__device__ __forceinline__ uint32_t taddr(uint32_t tile, int j0, int col0, int q, int lr) {
    return swaddr(tile, j0 + (q >> 1) * 8 + lr, (col0 + (q & 1) * 8) * 2);
}

// ---------------------------------------------------------------------------
// Converters (batched)
// ---------------------------------------------------------------------------
__global__ __launch_bounds__(256)
void conv_a_all(const float* __restrict__ X0, const float* __restrict__ X1,
                const float* __restrict__ X2, __half* __restrict__ Y)
{
    const int slab = blockIdx.y;
    const float* X = (slab == 0) ? X0 : (slab == 1) ? X1 : X2;
    const size_t i = ((size_t)blockIdx.x * 256 + threadIdx.x) * 4;
    float4 v = *(const float4*)(X + i);
    uint2 u;
    u.x = pack2(v.x, v.y);
    u.y = pack2(v.z, v.w);
    *(uint2*)(Y + (size_t)slab * M_ * DM + i) = u;
}

__global__ __launch_bounds__(256)
void conv_w_all(const float* __restrict__ W0, const float* __restrict__ W1,
                const float* __restrict__ W2, const float* __restrict__ W3,
                __half* __restrict__ Y)
{
    __shared__ float s[32][33];
    const int slab = blockIdx.z;
    const float* W = (slab == 0) ? W0 : (slab == 1) ? W1 : (slab == 2) ? W2 : W3;
    __half* Yo = Y + (size_t)slab * DM * DM;
    const int n0 = blockIdx.x * 32, k0 = blockIdx.y * 32;
    const int tx = threadIdx.x & 31, ty = threadIdx.x >> 5;
    #pragma unroll
    for (int i = 0; i < 4; i++)
        s[ty + i * 8][tx] = W[(size_t)(k0 + ty + i * 8) * DM + n0 + tx];
    __syncthreads();
    #pragma unroll
    for (int i = 0; i < 4; i++) {
        float x = s[tx][ty + i * 8];
        Yo[(size_t)(n0 + ty + i * 8) * DM + k0 + tx] = __float2half_rn(x);
    }
}

// ---------------------------------------------------------------------------
// fp16 tensor GEMM (validated R12/R13), fp32 or fp16 output, slab-batched.
// ---------------------------------------------------------------------------
__device__ __forceinline__ void load_chunk(
    const __half* A16, const __half* B16,
    size_t aRowBase, int n0, int tid, int ch, uint32_t stg)
{
    const int r0 = tid >> 3;
    const int c  = tid & 7;
    const uint32_t kbyte = (uint32_t)ch * (KC * 2);
    #pragma unroll
    for (int i = 0; i < 4; i++) {
        const int r = r0 + 32 * i;
        const uint32_t sw = swaddr(0, r, c * 16);
        cp16(stg + 0 * TILE_B + sw,
             (const char*)A16 + (aRowBase + r) * (DM * 2) + kbyte + c * 16);
        cp16(stg + 1 * TILE_B + sw,
             (const char*)B16 + (size_t)(n0 + r) * (DM * 2) + kbyte + c * 16);
    }
}

__global__ __launch_bounds__(256, 2)
void gemm_tc_kernel(const __half* __restrict__ A16,
                    const __half* __restrict__ W16,
                    const float* __restrict__ b0, const float* __restrict__ b1,
                    const float* __restrict__ b2,
                    void* C0v, void* C1v, void* C2v,
                    int actmask, int outhalf)
{
    extern __shared__ char smem[];
    const uint32_t sbase = smem_u32(smem);

    const int slab = blockIdx.z;
    const __half* B16 = W16 + (size_t)slab * DM * DM;
    const float* bias = (slab == 0) ? b0 : (slab == 1) ? b1 : b2;
    void* Cv = (slab == 0) ? C0v : (slab == 1) ? C1v : C2v;
    const int act = (actmask >> slab) & 1;

    const int tid  = threadIdx.x;
    const int wid  = tid >> 5, lane = tid & 31;
    const int wr   = wid & 3;
    const int wc   = wid >> 2;
    const int m0 = blockIdx.y * 128;
    const size_t aRowBase = (size_t)slab * M_ + m0;
    const int n0 = blockIdx.x * 128;

    const int q   = lane >> 3;
    const int lr  = lane & 7;
    const int kQ  = (q >> 1) * 16;

    float acc[2][8][4];
    #pragma unroll
    for (int mt = 0; mt < 2; mt++)
        #pragma unroll
        for (int nt = 0; nt < 8; nt++)
            #pragma unroll
            for (int e = 0; e < 4; e++) acc[mt][nt][e] = 0.f;

    load_chunk(A16, B16, aRowBase, n0, tid, 0, sbase + 0 * STG_B);
    CP_COMMIT();
    load_chunk(A16, B16, aRowBase, n0, tid, 1, sbase + 1 * STG_B);
    CP_COMMIT();

    for (int chk = 0; chk < KCHUNKS; chk++) {
        CP_WAIT1();
        __syncthreads();

        if (chk + 2 < KCHUNKS)
            load_chunk(A16, B16, aRowBase, n0, tid, chk + 2,
                       sbase + ((chk + 2) % NSTG) * STG_B);
        CP_COMMIT();

        const uint32_t stg = sbase + (chk % NSTG) * STG_B;
        const uint32_t tA  = stg + 0 * TILE_B;
        const uint32_t tB  = stg + 1 * TILE_B;

        #pragma unroll
        for (int k16 = 0; k16 < 4; k16++) {
            const int kb = k16 * 32 + kQ;
            uint32_t Af[2][4];
            #pragma unroll
            for (int mt = 0; mt < 2; mt++)
                ldsm4(Af[mt], swaddr(tA, wr * 32 + mt * 16 + (q & 1) * 8 + lr, kb));
            #pragma unroll
            for (int g = 0; g < 4; g++) {
                uint32_t Bf[4];
                ldsm4(Bf, swaddr(tB, wc * 64 + g * 16 + (q & 1) * 8 + lr, kb));
                #pragma unroll
                for (int s = 0; s < 2; s++) {
                    const int nt = g * 2 + s;
                    #pragma unroll
                    for (int mt = 0; mt < 2; mt++)
                        mma16816(acc[mt][nt], Af[mt], Bf[s], Bf[s + 2]);
                }
            }
        }
    }

    // epilogue
    #pragma unroll
    for (int mt = 0; mt < 2; mt++) {
        const int row = m0 + wr * 32 + mt * 16 + (lane >> 2);
        #pragma unroll
        for (int nt = 0; nt < 8; nt++) {
            const int col = n0 + wc * 64 + nt * 8 + 2 * (lane & 3);
            const float bb0 = bias[col], bb1 = bias[col + 1];
            float v0 = acc[mt][nt][0] + bb0;
            float v1 = acc[mt][nt][1] + bb1;
            float v2 = acc[mt][nt][2] + bb0;
            float v3 = acc[mt][nt][3] + bb1;
            if (act) {
                v0 = (v0 > 0.f) ? (v0 + 1.f) : expf(v0);
                v1 = (v1 > 0.f) ? (v1 + 1.f) : expf(v1);
                v2 = (v2 > 0.f) ? (v2 + 1.f) : expf(v2);
                v3 = (v3 > 0.f) ? (v3 + 1.f) : expf(v3);
            }
            if (outhalf) {
                __half* Ch = (__half*)Cv;
                *(uint32_t*)(Ch + (size_t)row * DM + col)       = pack2(v0, v1);
                *(uint32_t*)(Ch + (size_t)(row + 8) * DM + col) = pack2(v2, v3);
            } else {
                float* C = (float*)Cv;
                *(float2*)(C + (size_t)row * DM + col)       = make_float2(v0, v1);
                *(float2*)(C + (size_t)(row + 8) * DM + col) = make_float2(v2, v3);
            }
        }
    }
}

// ---------------------------------------------------------------------------
// Fused scan head: per (b,h) persistent CTA walks 32 chunks, mma-accumulating
// S in fp32 fragments. The accumulator value BEFORE adding chunk ch IS the
// exclusive prefix -> stored directly; prefix costs zero extra math.
// Z handled the same way with a register running sum. 128 threads, 4 warps.
// ---------------------------------------------------------------------------
__global__ __launch_bounds__(128, 1)
void attn_sums_prefix(const __half* __restrict__ K16,
                      const __half* __restrict__ V16,
                      float* __restrict__ S,
                      float* __restrict__ Z)
{
    __shared__ __align__(128) __half sK[2][64 * 64];
    __shared__ __align__(128) __half sV[2][64 * 64];
    __shared__ float sZp[2][64];

    const int bh = blockIdx.x;
    const int b = bh >> 4, h = bh & 15;
    const size_t hbase = (size_t)b * L_ * DM + h * HD;
    const int tid = threadIdx.x;
    const uint32_t uK0 = smem_u32(sK[0]), uV0 = smem_u32(sV[0]);

    const int wid = tid >> 5, lane = tid & 31;
    const int q = lane >> 3, lr = lane & 7;
    const int c0 = (wid >> 1) * 32, a0 = (wid & 1) * 32;

    // running S fragments (exclusive prefix lives here) + running Z
    float sacc[2][4][4];
    #pragma unroll
    for (int mt = 0; mt < 2; mt++)
        #pragma unroll
        for (int nt = 0; nt < 4; nt++)
            #pragma unroll
            for (int e = 0; e < 4; e++) sacc[mt][nt][e] = 0.f;
    float zrun = 0.f;

    // prologue: load chunk 0 into buf 0
    {
        const size_t base = hbase;
        for (int f = tid; f < 512; f += 128) {
            const int r = f >> 3, c = f & 7;
            const uint32_t sw = swaddr(0, r, c * 16);
            cp16(uK0 + sw, K16 + base + (size_t)r * DM + c * 8);
            cp16(uV0 + sw, V16 + base + (size_t)r * DM + c * 8);
        }
        CP_COMMIT();
    }

    for (int ch = 0; ch < NCH; ch++) {
        CP_WAIT0();
        __syncthreads();   // buf (ch&1) ready; all warps past chunk ch-1

        // issue load of chunk ch+1 into the other buffer
        if (ch + 1 < NCH) {
            const int nb = (ch + 1) & 1;
            const uint32_t uKn = smem_u32(sK[nb]), uVn = smem_u32(sV[nb]);
            const size_t base = hbase + (size_t)(ch + 1) * CH * DM;
            for (int f = tid; f < 512; f += 128) {
                const int r = f >> 3, c = f & 7;
                const uint32_t sw = swaddr(0, r, c * 16);
                cp16(uKn + sw, K16 + base + (size_t)r * DM + c * 8);
                cp16(uVn + sw, V16 + base + (size_t)r * DM + c * 8);
            }
        }
        CP_COMMIT();

        // store exclusive prefix for chunk ch (current accumulator values)
        {
            float* sout = S + ((size_t)bh * NCH + ch) * (HD * HD);
            #pragma unroll
            for (int mt = 0; mt < 2; mt++)
                #pragma unroll
                for (int nt = 0; nt < 4; nt++) {
                    const int c = c0 + mt * 16 + (lane >> 2);
                    const int a = a0 + nt * 8 + 2 * (lane & 3);
                    *(float2*)(sout + (size_t)c * HD + a) =
                        make_float2(sacc[mt][nt][0], sacc[mt][nt][1]);
                    *(float2*)(sout + (size_t)(c + 8) * HD + a) =
                        make_float2(sacc[mt][nt][2], sacc[mt][nt][3]);
                }
            if (tid < 64)
                Z[((size_t)bh * NCH + ch) * HD + tid] = zrun;
        }

        const int buf = ch & 1;
        const uint32_t uK = smem_u32(sK[buf]), uV = smem_u32(sV[buf]);

        // Z chunk sum: two 32-row halves per column, combined via smem
        {
            const int col = tid & 63, half = tid >> 6;
            float s32 = 0.f;
            #pragma unroll
            for (int i = 0; i < 32; i++)
                s32 += __half2float(
                    *(const __half*)((const char*)sK[buf] +
                                     swaddr(0, half * 32 + i, col * 2)));
            sZp[half][col] = s32;
        }

        // mma-accumulate chunk ch into sacc: S[c][a] += sum_j V[j][c] K[j][a]
        #pragma unroll
        for (int jk = 0; jk < 4; jk++) {
            uint32_t Af[2][4];
            #pragma unroll
            for (int mt = 0; mt < 2; mt++)
                ldsm4t(Af[mt], taddr(uV, jk * 16, c0 + mt * 16, q, lr));
            #pragma unroll
            for (int nb = 0; nb < 2; nb++) {
                uint32_t Bf[4];
                ldsm4t(Bf, taddr(uK, jk * 16, a0 + nb * 16, q, lr));
                #pragma unroll
                for (int s = 0; s < 2; s++)
                    #pragma unroll
                    for (int mt = 0; mt < 2; mt++)
                        mma16816(sacc[mt][nb * 2 + s], Af[mt], Bf[s], Bf[s + 2]);
            }
        }

        __syncthreads();   // sZp visible
        if (tid < 64) zrun += sZp[0][tid] + sZp[1][tid];
    }
}

// ---------------------------------------------------------------------------
// Scan kernel C: per-chunk outputs, tensorized (validated R13).
// ---------------------------------------------------------------------------
__global__ __launch_bounds__(256, 2)
void attn_chunk_out(const __half* __restrict__ Q16,
                    const __half* __restrict__ K16,
                    const __half* __restrict__ V16,
                    const float* __restrict__ Sp,
                    const float* __restrict__ Zp,
                    __half* __restrict__ O16)
{
    extern __shared__ char cosm[];
    const uint32_t ub = smem_u32(cosm);

    const int ch = blockIdx.x, bh = blockIdx.y;
    const int b = bh >> 4, h = bh & 15;
    const size_t base = ((size_t)(b * L_ + ch * CH)) * DM + h * HD;
    const int tid = threadIdx.x;

    for (int f = tid; f < 512; f += 256) {
        const int r = f >> 3, c = f & 7;
        const uint32_t sw = swaddr(0, r, c * 16);
        *(uint4*)(cosm + CO_Q + sw) = *(const uint4*)(Q16 + base + (size_t)r * DM + c * 8);
        *(uint4*)(cosm + CO_V + sw) = *(const uint4*)(V16 + base + (size_t)r * DM + c * 8);
        *(uint4*)(cosm + CO_K + sw) = *(const uint4*)(K16 + base + (size_t)r * DM + c * 8);
    }
    {
        const float* sp = Sp + ((size_t)bh * NCH + ch) * (HD * HD);
        #pragma unroll
        for (int it = 0; it < 4; it++) {
            const int e = (tid + it * 256) * 4;
            const int c = e >> 6, a = e & 63;
            float4 v = *(const float4*)(sp + (size_t)c * HD + a);
            uint2 u;
            u.x = pack2(v.x, v.y);
            u.y = pack2(v.z, v.w);
            *(uint2*)(cosm + CO_SP + swaddr(0, c, a * 2)) = u;
        }
    }
    __syncthreads();

    const int wid = tid >> 5, lane = tid & 31;
    const int q = lane >> 3, lr = lane & 7;
    const int wr = wid & 3, wc = wid >> 2;
    const int i0 = wr * 16, j0 = wc * 32;
    const bool active = (j0 <= i0 + 15);

    const uint32_t uQ = ub + CO_Q, uV = ub + CO_V, uK = ub + CO_K, uSp = ub + CO_SP;

    float numacc[8][4];
    #pragma unroll
    for (int nt = 0; nt < 8; nt++)
        #pragma unroll
        for (int e = 0; e < 4; e++) numacc[nt][e] = 0.f;

    if (active) {
        float gacc[4][4];
        #pragma unroll
        for (int nt = 0; nt < 4; nt++)
            #pragma unroll
            for (int e = 0; e < 4; e++) gacc[nt][e] = 0.f;

        #pragma unroll
        for (int kc = 0; kc < 4; kc++) {
            const int kb = kc * 32 + (q >> 1) * 16;
            uint32_t Aq[4];
            ldsm4(Aq, naddr(uQ, i0, kc * 32, q, lr));
            #pragma unroll
            for (int g = 0; g < 2; g++) {
                uint32_t Bv[4];
                ldsm4(Bv, swaddr(uV, j0 + g * 16 + (q & 1) * 8 + lr, kb));
                mma16816(gacc[g * 2 + 0], Aq, Bv[0], Bv[2]);
                mma16816(gacc[g * 2 + 1], Aq, Bv[1], Bv[3]);
            }
            if (wc == 0) {
                #pragma unroll
                for (int nb = 0; nb < 4; nb++) {
                    uint32_t Bs[4];
                    ldsm4t(Bs, taddr(uSp, kc * 16, nb * 16, q, lr));
                    mma16816(numacc[nb * 2 + 0], Aq, Bs[0], Bs[2]);
                    mma16816(numacc[nb * 2 + 1], Aq, Bs[1], Bs[3]);
                }
            }
        }

        #pragma unroll
        for (int nt = 0; nt < 4; nt++) {
            const int jb = j0 + nt * 8 + 2 * (lane & 3);
            const int ib = i0 + (lane >> 2);
            if (jb     > ib)     gacc[nt][0] = 0.f;
            if (jb + 1 > ib)     gacc[nt][1] = 0.f;
            if (jb     > ib + 8) gacc[nt][2] = 0.f;
            if (jb + 1 > ib + 8) gacc[nt][3] = 0.f;
        }
        uint32_t aG[2][4];
        #pragma unroll
        for (int t = 0; t < 2; t++) {
            aG[t][0] = pack2(gacc[2 * t][0],     gacc[2 * t][1]);
            aG[t][1] = pack2(gacc[2 * t][2],     gacc[2 * t][3]);
            aG[t][2] = pack2(gacc[2 * t + 1][0], gacc[2 * t + 1][1]);
            aG[t][3] = pack2(gacc[2 * t + 1][2], gacc[2 * t + 1][3]);
        }
        #pragma unroll
        for (int t = 0; t < 2; t++)
            #pragma unroll
            for (int nb = 0; nb < 4; nb++) {
                uint32_t Bk[4];
                ldsm4t(Bk, taddr(uK, j0 + t * 16, nb * 16, q, lr));
                mma16816(numacc[nb * 2 + 0], aG[t], Bk[0], Bk[2]);
                mma16816(numacc[nb * 2 + 1], aG[t], Bk[1], Bk[3]);
            }
    }

    if (wc == 1 && wr >= 2) {
        float* red = (float*)(cosm + CO_RED) + (size_t)(wr - 2) * 16 * 68;
        #pragma unroll
        for (int nt = 0; nt < 8; nt++) {
            const int r = lane >> 2, a = nt * 8 + 2 * (lane & 3);
            *(float2*)(red + r * 68 + a)       = make_float2(numacc[nt][0], numacc[nt][1]);
            *(float2*)(red + (r + 8) * 68 + a) = make_float2(numacc[nt][2], numacc[nt][3]);
        }
    }
    __syncthreads();

    if (wc == 0) {
        if (wr >= 2) {
            const float* red = (const float*)(cosm + CO_RED) + (size_t)(wr - 2) * 16 * 68;
            #pragma unroll
            for (int nt = 0; nt < 8; nt++) {
                const int r = lane >> 2, a = nt * 8 + 2 * (lane & 3);
                float2 p0 = *(const float2*)(red + r * 68 + a);
                float2 p1 = *(const float2*)(red + (r + 8) * 68 + a);
                numacc[nt][0] += p0.x; numacc[nt][1] += p0.y;
                numacc[nt][2] += p1.x; numacc[nt][3] += p1.y;
            }
        }
        float* nm = (float*)(cosm + CO_NUM);
        #pragma unroll
        for (int nt = 0; nt < 8; nt++) {
            const int r = wr * 16 + (lane >> 2), a = nt * 8 + 2 * (lane & 3);
            *(float2*)(nm + r * 72 + a)       = make_float2(numacc[nt][0], numacc[nt][1]);
            *(float2*)(nm + (r + 8) * 72 + a) = make_float2(numacc[nt][2], numacc[nt][3]);
        }
    }
    __syncthreads();

    {
        const int az = tid & 63, seg = tid >> 6;
        float s16 = 0.f;
        #pragma unroll
        for (int i2 = 0; i2 < 16; i2++)
            s16 += __half2float(*(const __half*)(cosm + CO_K + swaddr(0, seg * 16 + i2, az * 2)));
        float* part = (float*)(cosm + CO_PART);
        part[seg * 64 + az] = s16;
        __syncthreads();
        float run = Zp[((size_t)bh * NCH + ch) * HD + az];
        #pragma unroll
        for (int s2 = 0; s2 < 3; s2++)
            if (s2 < seg) run += part[s2 * 64 + az];
        float* zw = (float*)(cosm + CO_ZW);
        #pragma unroll
        for (int i2 = 0; i2 < 16; i2++) {
            run += __half2float(*(const __half*)(cosm + CO_K + swaddr(0, seg * 16 + i2, az * 2)));
            zw[(seg * 16 + i2) * 64 + az] = run;
        }
    }
    __syncthreads();

    {
        const int tx = tid & 15, ty = tid >> 4;
        const float* nm = (const float*)(cosm + CO_NUM);
        const float* zw = (const float*)(cosm + CO_ZW);
        #pragma unroll
        for (int ii = 0; ii < 4; ii++) {
            const int i = ty * 4 + ii;
            float4 n4 = *(const float4*)(nm + i * 72 + tx * 4);
            float4 z4 = *(const float4*)(zw + i * 64 + tx * 4);
            unsigned short o[4];
            #pragma unroll
            for (int aa = 0; aa < 4; aa++) {
                const int a = tx * 4 + aa;
                const float qv = __half2float(
                    *(const __half*)(cosm + CO_Q + swaddr(0, i, a * 2)));
                o[aa] = __half_as_ushort(
                    __float2half_rn((&n4.x)[aa] / (qv * (&z4.x)[aa] + EPSC)));
            }
            uint2 u;
            u.x = (uint32_t)o[0] | ((uint32_t)o[1] << 16);
            u.y = (uint32_t)o[2] | ((uint32_t)o[3] << 16);
            *(uint2*)(O16 + base + (size_t)i * DM + tx * 4) = u;
        }
    }
}

// ---------------------------------------------------------------------------
// kernel_launch — sequential (R13 schedule) with fused scan head.
// ---------------------------------------------------------------------------
extern "C" void kernel_launch(void* const* d_in, const int* in_sizes, int n_in,
                              void* d_out, int out_size)
{
    const float* queries = (const float*)d_in[0];
    const float* keys    = (const float*)d_in[1];
    const float* values  = (const float*)d_in[2];
    const float* Wq = (const float*)d_in[3];
    const float* bq = (const float*)d_in[4];
    const float* Wk = (const float*)d_in[5];
    const float* bk = (const float*)d_in[6];
    const float* Wv = (const float*)d_in[7];
    const float* bv = (const float*)d_in[8];
    const float* Wo = (const float*)d_in[9];
    const float* bo = (const float*)d_in[10];
    float* out = (float*)d_out;

    float *pS, *pZ;
    __half *pA16, *pW16, *pQ16, *pK16, *pV16;
    cudaGetSymbolAddress((void**)&pS, g_S);
    cudaGetSymbolAddress((void**)&pZ, g_Z);
    cudaGetSymbolAddress((void**)&pA16, g_A16);
    cudaGetSymbolAddress((void**)&pW16, g_W16);
    cudaGetSymbolAddress((void**)&pQ16, g_Q16);
    cudaGetSymbolAddress((void**)&pK16, g_K16);
    cudaGetSymbolAddress((void**)&pV16, g_V16);

    cudaFuncSetAttribute(gemm_tc_kernel,
                         cudaFuncAttributeMaxDynamicSharedMemorySize, SMEM_GEMM);
    cudaFuncSetAttribute(attn_chunk_out,
                         cudaFuncAttributeMaxDynamicSharedMemorySize, CO_SMEM);

    const dim3 chunk_grid(NCH, B_ * H_);

    // 1) weight converts (4 slabs)
    conv_w_all<<<dim3(DM / 32, DM / 32, 4), 256>>>(Wq, Wk, Wv, Wo, pW16);
    // 2) input converts (3 slabs)
    conv_a_all<<<dim3(M_ * DM / 1024, 3), 256>>>(queries, keys, values, pA16);
    // 3) projections -> fp16 Q,K,V (act on q,k)
    gemm_tc_kernel<<<dim3(DM / 128, M_ / 128, 3), 256, SMEM_GEMM>>>(
        pA16, pW16, bq, bk, bv, pQ16, pK16, pV16, 0b011, 1);
    // 4) fused chunk sums + exclusive prefix (persistent per-(b,h) CTAs)
    attn_sums_prefix<<<B_ * H_, 128>>>(pK16, pV16, pS, pZ);
    // 5) per-chunk outputs -> fp16 A16 slab 0
    attn_chunk_out<<<chunk_grid, 256, CO_SMEM>>>(pQ16, pK16, pV16, pS, pZ, pA16);
    // 6) output projection (W slab 3), fp32 out
    gemm_tc_kernel<<<dim3(DM / 128, M_ / 128, 1), 256, SMEM_GEMM>>>(
        pA16, pW16 + (size_t)3 * DM * DM, bo, bo, bo, out, out, out, 0, 0);
}

// round 16
// speedup vs baseline: 1.1357x; 1.0073x over previous
#include <cuda_runtime.h>
#include <cuda_fp16.h>
#include <cstdint>
#include <math.h>

// Problem constants
#define B_   4
#define L_   2048
#define DM   1024
#define H_   16
#define HD   64
#define M_   (B_ * L_)       // 8192 rows
#define EPSC 1e-6f
#define CH   64              // scan chunk length
#define NCH  (L_ / CH)       // 32 chunks

// GEMM constants (validated shape): CTA 128x128, warp tile 32x64, BK=64
#define KC        64
#define KCHUNKS   (DM / KC)           // 16
#define TILE_B    16384               // 128-row x 128-byte tile
#define STG_B     (2 * TILE_B)        // 32 KB
#define NSTG      3
#define SMEM_GEMM (NSTG * STG_B)      // 96 KB, occ 2

// chunk_out dynamic smem layout (bytes)
#define CO_Q    0
#define CO_V    8192
#define CO_K    16384
#define CO_SP   24576
#define CO_NUM  32768                       // float [64][72]
#define CO_ZW   (CO_NUM + 64 * 72 * 4)      // 51200: float [64][64]
#define CO_RED  (CO_ZW + 64 * 64 * 4)       // 67584: float [2][16][68]
#define CO_PART (CO_RED + 2 * 16 * 68 * 4)  // 76288: float [4][64]
#define CO_SMEM (CO_PART + 4 * 64 * 4)      // 77312

#define CONVA_BLOCKS (M_ * DM / 1024)       // 8192 blocks per input slab

// ---------------------------------------------------------------------------
// Scratch (allocation-free rule: __device__ globals)
// ---------------------------------------------------------------------------
__device__ float  g_S[(size_t)B_ * H_ * NCH * HD * HD]; // exclusive-prefix S
__device__ float  g_Z[(size_t)B_ * H_ * NCH * HD];      // exclusive-prefix Z
__device__ __half g_A16[(size_t)3 * M_ * DM];           // fp16 A slabs (in / attn out)
__device__ __half g_W16[(size_t)4 * DM * DM];           // [N,K] fp16, 4 slabs
__device__ __half g_Q16[(size_t)M_ * DM];
__device__ __half g_K16[(size_t)M_ * DM];
__device__ __half g_V16[(size_t)M_ * DM];

// ---------------------------------------------------------------------------
// PTX helpers (base-target sm_103-safe)
// ---------------------------------------------------------------------------
__device__ __forceinline__ uint32_t smem_u32(const void* p) {
    uint32_t a;
    asm("{ .reg .u64 t; cvta.to.shared.u64 t, %1; cvt.u32.u64 %0, t; }" : "=r"(a) : "l"(p));
    return a;
}
__device__ __forceinline__ void cp16(uint32_t saddr, const void* g) {
    asm volatile("cp.async.cg.shared.global [%0], [%1], 16;\n" :: "r"(saddr), "l"(g));
}
#define CP_COMMIT() asm volatile("cp.async.commit_group;\n")
#define CP_WAIT0()  asm volatile("cp.async.wait_group 0;\n")
#define CP_WAIT1()  asm volatile("cp.async.wait_group 1;\n")

__device__ __forceinline__ void ldsm4(uint32_t* r, uint32_t addr) {
    asm volatile("ldmatrix.sync.aligned.m8n8.x4.shared.b16 {%0,%1,%2,%3}, [%4];"
                 : "=r"(r[0]), "=r"(r[1]), "=r"(r[2]), "=r"(r[3]) : "r"(addr));
}
__device__ __forceinline__ void ldsm4t(uint32_t* r, uint32_t addr) {
    asm volatile("ldmatrix.sync.aligned.m8n8.x4.trans.shared.b16 {%0,%1,%2,%3}, [%4];"
                 : "=r"(r[0]), "=r"(r[1]), "=r"(r[2]), "=r"(r[3]) : "r"(addr));
}
__device__ __forceinline__ void mma16816(float* d, const uint32_t* a,
                                         uint32_t b0, uint32_t b1) {
    asm volatile(
        "mma.sync.aligned.m16n8k16.row.col.f32.f16.f16.f32 "
        "{%0,%1,%2,%3}, {%4,%5,%6,%7}, {%8,%9}, {%0,%1,%2,%3};"
        : "+f"(d[0]), "+f"(d[1]), "+f"(d[2]), "+f"(d[3])
        : "r"(a[0]), "r"(a[1]), "r"(a[2]), "r"(a[3]), "r"(b0), "r"(b1));
}
__device__ __forceinline__ uint32_t pack2(float lo, float hi) {
    uint32_t d;
    asm("cvt.rn.f16x2.f32 %0, %1, %2;" : "=r"(d) : "f"(hi), "f"(lo));
    return d;
}

// SW128 swizzle within a tile of 128-byte rows
__device__ __forceinline__ uint32_t swaddr(uint32_t tilebase, int row, int cbyte) {
    uint32_t off = ((uint32_t)(row >> 3) << 10) + ((uint32_t)(row & 7) << 7)
                 + (uint32_t)cbyte;
    return tilebase + (off ^ ((off >> 3) & 0x70u));
}
// Fragment source address: row-major operand [r][k]
__device__ __forceinline__ uint32_t naddr(uint32_t tile, int r0, int kb, int q, int lr) {
    return swaddr(tile, r0 + (q & 1) * 8 + lr, kb + (q >> 1) * 16);
}
// Trans fragment: smem holds T[j][col]; want op[m_or_n=col][k=j]
__device__ __forceinline__ uint32_t taddr(uint32_t tile, int j0, int col0, int q, int lr) {
    return swaddr(tile, j0 + (q >> 1) * 8 + lr, (col0 + (q & 1) * 8) * 2);
}

// ---------------------------------------------------------------------------
// Merged converter: one launch covers 3 input slabs + 4 weight slabs.
// Blocks [0, 3*CONVA_BLOCKS): fp32 -> fp16 input convert.
// Blocks [3*CONVA_BLOCKS, +4096): W [K,N] fp32 -> transposed [N,K] fp16.
// ---------------------------------------------------------------------------
__global__ __launch_bounds__(256)
void conv_all(const float* __restrict__ X0, const float* __restrict__ X1,
              const float* __restrict__ X2,
              const float* __restrict__ W0, const float* __restrict__ W1,
              const float* __restrict__ W2, const float* __restrict__ W3,
              __half* __restrict__ YA, __half* __restrict__ YW)
{
    __shared__ float s[32][33];
    const int bid = blockIdx.x;
    if (bid < 3 * CONVA_BLOCKS) {
        const int slab = bid / CONVA_BLOCKS;
        const int ib   = bid - slab * CONVA_BLOCKS;
        const float* X = (slab == 0) ? X0 : (slab == 1) ? X1 : X2;
        const size_t i = ((size_t)ib * 256 + threadIdx.x) * 4;
        float4 v = *(const float4*)(X + i);
        uint2 u;
        u.x = pack2(v.x, v.y);
        u.y = pack2(v.z, v.w);
        *(uint2*)(YA + (size_t)slab * M_ * DM + i) = u;
    } else {
        const int wb   = bid - 3 * CONVA_BLOCKS;      // 0..4095
        const int slab = wb >> 10;
        const int rem  = wb & 1023;
        const float* W = (slab == 0) ? W0 : (slab == 1) ? W1
                         : (slab == 2) ? W2 : W3;
        __half* Yo = YW + (size_t)slab * DM * DM;
        const int n0 = (rem & 31) * 32, k0 = (rem >> 5) * 32;
        const int tx = threadIdx.x & 31, ty = threadIdx.x >> 5;
        #pragma unroll
        for (int i = 0; i < 4; i++)
            s[ty + i * 8][tx] = W[(size_t)(k0 + ty + i * 8) * DM + n0 + tx];
        __syncthreads();
        #pragma unroll
        for (int i = 0; i < 4; i++) {
            float x = s[tx][ty + i * 8];
            Yo[(size_t)(n0 + ty + i * 8) * DM + k0 + tx] = __float2half_rn(x);
        }
    }
}

// ---------------------------------------------------------------------------
// fp16 tensor GEMM (validated R12/R13), fp32 or fp16 output, slab-batched.
// ---------------------------------------------------------------------------
__device__ __forceinline__ void load_chunk(
    const __half* A16, const __half* B16,
    size_t aRowBase, int n0, int tid, int ch, uint32_t stg)
{
    const int r0 = tid >> 3;
    const int c  = tid & 7;
    const uint32_t kbyte = (uint32_t)ch * (KC * 2);
    #pragma unroll
    for (int i = 0; i < 4; i++) {
        const int r = r0 + 32 * i;
        const uint32_t sw = swaddr(0, r, c * 16);
        cp16(stg + 0 * TILE_B + sw,
             (const char*)A16 + (aRowBase + r) * (DM * 2) + kbyte + c * 16);
        cp16(stg + 1 * TILE_B + sw,
             (const char*)B16 + (size_t)(n0 + r) * (DM * 2) + kbyte + c * 16);
    }
}

__global__ __launch_bounds__(256, 2)
void gemm_tc_kernel(const __half* __restrict__ A16,
                    const __half* __restrict__ W16,
                    const float* __restrict__ b0, const float* __restrict__ b1,
                    const float* __restrict__ b2,
                    void* C0v, void* C1v, void* C2v,
                    int actmask, int outhalf)
{
    extern __shared__ char smem[];
    const uint32_t sbase = smem_u32(smem);

    const int slab = blockIdx.z;
    const __half* B16 = W16 + (size_t)slab * DM * DM;
    const float* bias = (slab == 0) ? b0 : (slab == 1) ? b1 : b2;
    void* Cv = (slab == 0) ? C0v : (slab == 1) ? C1v : C2v;
    const int act = (actmask >> slab) & 1;

    const int tid  = threadIdx.x;
    const int wid  = tid >> 5, lane = tid & 31;
    const int wr   = wid & 3;
    const int wc   = wid >> 2;
    const int m0 = blockIdx.y * 128;
    const size_t aRowBase = (size_t)slab * M_ + m0;
    const int n0 = blockIdx.x * 128;

    const int q   = lane >> 3;
    const int lr  = lane & 7;
    const int kQ  = (q >> 1) * 16;

    float acc[2][8][4];
    #pragma unroll
    for (int mt = 0; mt < 2; mt++)
        #pragma unroll
        for (int nt = 0; nt < 8; nt++)
            #pragma unroll
            for (int e = 0; e < 4; e++) acc[mt][nt][e] = 0.f;

    load_chunk(A16, B16, aRowBase, n0, tid, 0, sbase + 0 * STG_B);
    CP_COMMIT();
    load_chunk(A16, B16, aRowBase, n0, tid, 1, sbase + 1 * STG_B);
    CP_COMMIT();

    for (int chk = 0; chk < KCHUNKS; chk++) {
        CP_WAIT1();
        __syncthreads();

        if (chk + 2 < KCHUNKS)
            load_chunk(A16, B16, aRowBase, n0, tid, chk + 2,
                       sbase + ((chk + 2) % NSTG) * STG_B);
        CP_COMMIT();

        const uint32_t stg = sbase + (chk % NSTG) * STG_B;
        const uint32_t tA  = stg + 0 * TILE_B;
        const uint32_t tB  = stg + 1 * TILE_B;

        #pragma unroll
        for (int k16 = 0; k16 < 4; k16++) {
            const int kb = k16 * 32 + kQ;
            uint32_t Af[2][4];
            #pragma unroll
            for (int mt = 0; mt < 2; mt++)
                ldsm4(Af[mt], swaddr(tA, wr * 32 + mt * 16 + (q & 1) * 8 + lr, kb));
            #pragma unroll
            for (int g = 0; g < 4; g++) {
                uint32_t Bf[4];
                ldsm4(Bf, swaddr(tB, wc * 64 + g * 16 + (q & 1) * 8 + lr, kb));
                #pragma unroll
                for (int s = 0; s < 2; s++) {
                    const int nt = g * 2 + s;
                    #pragma unroll
                    for (int mt = 0; mt < 2; mt++)
                        mma16816(acc[mt][nt], Af[mt], Bf[s], Bf[s + 2]);
                }
            }
        }
    }

    // epilogue
    #pragma unroll
    for (int mt = 0; mt < 2; mt++) {
        const int row = m0 + wr * 32 + mt * 16 + (lane >> 2);
        #pragma unroll
        for (int nt = 0; nt < 8; nt++) {
            const int col = n0 + wc * 64 + nt * 8 + 2 * (lane & 3);
            const float bb0 = bias[col], bb1 = bias[col + 1];
            float v0 = acc[mt][nt][0] + bb0;
            float v1 = acc[mt][nt][1] + bb1;
            float v2 = acc[mt][nt][2] + bb0;
            float v3 = acc[mt][nt][3] + bb1;
            if (act) {
                v0 = (v0 > 0.f) ? (v0 + 1.f) : expf(v0);
                v1 = (v1 > 0.f) ? (v1 + 1.f) : expf(v1);
                v2 = (v2 > 0.f) ? (v2 + 1.f) : expf(v2);
                v3 = (v3 > 0.f) ? (v3 + 1.f) : expf(v3);
            }
            if (outhalf) {
                __half* Ch = (__half*)Cv;
                *(uint32_t*)(Ch + (size_t)row * DM + col)       = pack2(v0, v1);
                *(uint32_t*)(Ch + (size_t)(row + 8) * DM + col) = pack2(v2, v3);
            } else {
                float* C = (float*)Cv;
                *(float2*)(C + (size_t)row * DM + col)       = make_float2(v0, v1);
                *(float2*)(C + (size_t)(row + 8) * DM + col) = make_float2(v2, v3);
            }
        }
    }
}

// ---------------------------------------------------------------------------
// Fused scan head (widened): per (b,h) persistent CTA, 256 threads, 8 warps
// (warp tile 16c x 32a). Accumulator BEFORE adding chunk ch == exclusive
// prefix -> stored directly. Z via 4-segment partials + register running sum.
// ---------------------------------------------------------------------------
__global__ __launch_bounds__(256, 1)
void attn_sums_prefix(const __half* __restrict__ K16,
                      const __half* __restrict__ V16,
                      float* __restrict__ S,
                      float* __restrict__ Z)
{
    __shared__ __align__(128) __half sK[2][64 * 64];
    __shared__ __align__(128) __half sV[2][64 * 64];
    __shared__ float sZp[4][64];

    const int bh = blockIdx.x;
    const int b = bh >> 4, h = bh & 15;
    const size_t hbase = (size_t)b * L_ * DM + h * HD;
    const int tid = threadIdx.x;
    const uint32_t uK0 = smem_u32(sK[0]), uV0 = smem_u32(sV[0]);

    const int wid = tid >> 5, lane = tid & 31;
    const int q = lane >> 3, lr = lane & 7;
    const int c0 = (wid >> 1) * 16;   // 4 c-tiles of 16
    const int a0 = (wid & 1) * 32;    // 2 a-tiles of 32

    float sacc[4][4];                 // 1 m-tile x 4 n8-tiles
    #pragma unroll
    for (int nt = 0; nt < 4; nt++)
        #pragma unroll
        for (int e = 0; e < 4; e++) sacc[nt][e] = 0.f;
    float zrun = 0.f;

    // prologue: chunk 0 into buf 0 (1024 flits over 256 threads)
    for (int f = tid; f < 512; f += 256) {
        const int r = f >> 3, c = f & 7;
        const uint32_t sw = swaddr(0, r, c * 16);
        cp16(uK0 + sw, K16 + hbase + (size_t)r * DM + c * 8);
        cp16(uV0 + sw, V16 + hbase + (size_t)r * DM + c * 8);
    }
    CP_COMMIT();

    for (int ch = 0; ch < NCH; ch++) {
        CP_WAIT0();
        __syncthreads();   // buf (ch&1) ready; all warps past chunk ch-1

        // issue load of chunk ch+1 into the other buffer
        if (ch + 1 < NCH) {
            const int nb = (ch + 1) & 1;
            const uint32_t uKn = smem_u32(sK[nb]), uVn = smem_u32(sV[nb]);
            const size_t base = hbase + (size_t)(ch + 1) * CH * DM;
            for (int f = tid; f < 512; f += 256) {
                const int r = f >> 3, c = f & 7;
                const uint32_t sw = swaddr(0, r, c * 16);
                cp16(uKn + sw, K16 + base + (size_t)r * DM + c * 8);
                cp16(uVn + sw, V16 + base + (size_t)r * DM + c * 8);
            }
        }
        CP_COMMIT();

        // store exclusive prefix for chunk ch (current accumulator values)
        {
            float* sout = S + ((size_t)bh * NCH + ch) * (HD * HD);
            #pragma unroll
            for (int nt = 0; nt < 4; nt++) {
                const int c = c0 + (lane >> 2);
                const int a = a0 + nt * 8 + 2 * (lane & 3);
                *(float2*)(sout + (size_t)c * HD + a) =
                    make_float2(sacc[nt][0], sacc[nt][1]);
                *(float2*)(sout + (size_t)(c + 8) * HD + a) =
                    make_float2(sacc[nt][2], sacc[nt][3]);
            }
            if (tid < 64)
                Z[((size_t)bh * NCH + ch) * HD + tid] = zrun;
        }

        const int buf = ch & 1;
        const uint32_t uK = smem_u32(sK[buf]), uV = smem_u32(sV[buf]);

        // Z chunk partials: 4 segments of 16 rows per column
        {
            const int col = tid & 63, seg = tid >> 6;
            float s16 = 0.f;
            #pragma unroll
            for (int i = 0; i < 16; i++)
                s16 += __half2float(
                    *(const __half*)((const char*)sK[buf] +
                                     swaddr(0, seg * 16 + i, col * 2)));
            sZp[seg][col] = s16;
        }

        // mma-accumulate chunk ch: S[c][a] += sum_j V[j][c] K[j][a]
        #pragma unroll
        for (int jk = 0; jk < 4; jk++) {
            uint32_t Af[4];
            ldsm4t(Af, taddr(uV, jk * 16, c0, q, lr));
            #pragma unroll
            for (int nb = 0; nb < 2; nb++) {
                uint32_t Bf[4];
                ldsm4t(Bf, taddr(uK, jk * 16, a0 + nb * 16, q, lr));
                mma16816(sacc[nb * 2 + 0], Af, Bf[0], Bf[2]);
                mma16816(sacc[nb * 2 + 1], Af, Bf[1], Bf[3]);
            }
        }

        __syncthreads();   // sZp visible
        if (tid < 64)
            zrun += sZp[0][tid] + sZp[1][tid] + sZp[2][tid] + sZp[3][tid];
    }
}

// ---------------------------------------------------------------------------
// Scan kernel C: per-chunk outputs, tensorized (validated R13).
// ---------------------------------------------------------------------------
__global__ __launch_bounds__(256, 2)
void attn_chunk_out(const __half* __restrict__ Q16,
                    const __half* __restrict__ K16,
                    const __half* __restrict__ V16,
                    const float* __restrict__ Sp,
                    const float* __restrict__ Zp,
                    __half* __restrict__ O16)
{
    extern __shared__ char cosm[];
    const uint32_t ub = smem_u32(cosm);

    const int ch = blockIdx.x, bh = blockIdx.y;
    const int b = bh >> 4, h = bh & 15;
    const size_t base = ((size_t)(b * L_ + ch * CH)) * DM + h * HD;
    const int tid = threadIdx.x;

    for (int f = tid; f < 512; f += 256) {
        const int r = f >> 3, c = f & 7;
        const uint32_t sw = swaddr(0, r, c * 16);
        *(uint4*)(cosm + CO_Q + sw) = *(const uint4*)(Q16 + base + (size_t)r * DM + c * 8);
        *(uint4*)(cosm + CO_V + sw) = *(const uint4*)(V16 + base + (size_t)r * DM + c * 8);
        *(uint4*)(cosm + CO_K + sw) = *(const uint4*)(K16 + base + (size_t)r * DM + c * 8);
    }
    {
        const float* sp = Sp + ((size_t)bh * NCH + ch) * (HD * HD);
        #pragma unroll
        for (int it = 0; it < 4; it++) {
            const int e = (tid + it * 256) * 4;
            const int c = e >> 6, a = e & 63;
            float4 v = *(const float4*)(sp + (size_t)c * HD + a);
            uint2 u;
            u.x = pack2(v.x, v.y);
            u.y = pack2(v.z, v.w);
            *(uint2*)(cosm + CO_SP + swaddr(0, c, a * 2)) = u;
        }
    }
    __syncthreads();

    const int wid = tid >> 5, lane = tid & 31;
    const int q = lane >> 3, lr = lane & 7;
    const int wr = wid & 3, wc = wid >> 2;
    const int i0 = wr * 16, j0 = wc * 32;
    const bool active = (j0 <= i0 + 15);

    const uint32_t uQ = ub + CO_Q, uV = ub + CO_V, uK = ub + CO_K, uSp = ub + CO_SP;

    float numacc[8][4];
    #pragma unroll
    for (int nt = 0; nt < 8; nt++)
        #pragma unroll
        for (int e = 0; e < 4; e++) numacc[nt][e] = 0.f;

    if (active) {
        float gacc[4][4];
        #pragma unroll
        for (int nt = 0; nt < 4; nt++)
            #pragma unroll
            for (int e = 0; e < 4; e++) gacc[nt][e] = 0.f;

        #pragma unroll
        for (int kc = 0; kc < 4; kc++) {
            const int kb = kc * 32 + (q >> 1) * 16;
            uint32_t Aq[4];
            ldsm4(Aq, naddr(uQ, i0, kc * 32, q, lr));
            #pragma unroll
            for (int g = 0; g < 2; g++) {
                uint32_t Bv[4];
                ldsm4(Bv, swaddr(uV, j0 + g * 16 + (q & 1) * 8 + lr, kb));
                mma16816(gacc[g * 2 + 0], Aq, Bv[0], Bv[2]);
                mma16816(gacc[g * 2 + 1], Aq, Bv[1], Bv[3]);
            }
            if (wc == 0) {
                #pragma unroll
                for (int nb = 0; nb < 4; nb++) {
                    uint32_t Bs[4];
                    ldsm4t(Bs, taddr(uSp, kc * 16, nb * 16, q, lr));
                    mma16816(numacc[nb * 2 + 0], Aq, Bs[0], Bs[2]);
                    mma16816(numacc[nb * 2 + 1], Aq, Bs[1], Bs[3]);
                }
            }
        }

        #pragma unroll
        for (int nt = 0; nt < 4; nt++) {
            const int jb = j0 + nt * 8 + 2 * (lane & 3);
            const int ib = i0 + (lane >> 2);
            if (jb     > ib)     gacc[nt][0] = 0.f;
            if (jb + 1 > ib)     gacc[nt][1] = 0.f;
            if (jb     > ib + 8) gacc[nt][2] = 0.f;
            if (jb + 1 > ib + 8) gacc[nt][3] = 0.f;
        }
        uint32_t aG[2][4];
        #pragma unroll
        for (int t = 0; t < 2; t++) {
            aG[t][0] = pack2(gacc[2 * t][0],     gacc[2 * t][1]);
            aG[t][1] = pack2(gacc[2 * t][2],     gacc[2 * t][3]);
            aG[t][2] = pack2(gacc[2 * t + 1][0], gacc[2 * t + 1][1]);
            aG[t][3] = pack2(gacc[2 * t + 1][2], gacc[2 * t + 1][3]);
        }
        #pragma unroll
        for (int t = 0; t < 2; t++)
            #pragma unroll
            for (int nb = 0; nb < 4; nb++) {
                uint32_t Bk[4];
                ldsm4t(Bk, taddr(uK, j0 + t * 16, nb * 16, q, lr));
                mma16816(numacc[nb * 2 + 0], aG[t], Bk[0], Bk[2]);
                mma16816(numacc[nb * 2 + 1], aG[t], Bk[1], Bk[3]);
            }
    }

    if (wc == 1 && wr >= 2) {
        float* red = (float*)(cosm + CO_RED) + (size_t)(wr - 2) * 16 * 68;
        #pragma unroll
        for (int nt = 0; nt < 8; nt++) {
            const int r = lane >> 2, a = nt * 8 + 2 * (lane & 3);
            *(float2*)(red + r * 68 + a)       = make_float2(numacc[nt][0], numacc[nt][1]);
            *(float2*)(red + (r + 8) * 68 + a) = make_float2(numacc[nt][2], numacc[nt][3]);
        }
    }
    __syncthreads();

    if (wc == 0) {
        if (wr >= 2) {
            const float* red = (const float*)(cosm + CO_RED) + (size_t)(wr - 2) * 16 * 68;
            #pragma unroll
            for (int nt = 0; nt < 8; nt++) {
                const int r = lane >> 2, a = nt * 8 + 2 * (lane & 3);
                float2 p0 = *(const float2*)(red + r * 68 + a);
                float2 p1 = *(const float2*)(red + (r + 8) * 68 + a);
                numacc[nt][0] += p0.x; numacc[nt][1] += p0.y;
                numacc[nt][2] += p1.x; numacc[nt][3] += p1.y;
            }
        }
        float* nm = (float*)(cosm + CO_NUM);
        #pragma unroll
        for (int nt = 0; nt < 8; nt++) {
            const int r = wr * 16 + (lane >> 2), a = nt * 8 + 2 * (lane & 3);
            *(float2*)(nm + r * 72 + a)       = make_float2(numacc[nt][0], numacc[nt][1]);
            *(float2*)(nm + (r + 8) * 72 + a) = make_float2(numacc[nt][2], numacc[nt][3]);
        }
    }
    __syncthreads();

    {
        const int az = tid & 63, seg = tid >> 6;
        float s16 = 0.f;
        #pragma unroll
        for (int i2 = 0; i2 < 16; i2++)
            s16 += __half2float(*(const __half*)(cosm + CO_K + swaddr(0, seg * 16 + i2, az * 2)));
        float* part = (float*)(cosm + CO_PART);
        part[seg * 64 + az] = s16;
        __syncthreads();
        float run = Zp[((size_t)bh * NCH + ch) * HD + az];
        #pragma unroll
        for (int s2 = 0; s2 < 3; s2++)
            if (s2 < seg) run += part[s2 * 64 + az];
        float* zw = (float*)(cosm + CO_ZW);
        #pragma unroll
        for (int i2 = 0; i2 < 16; i2++) {
            run += __half2float(*(const __half*)(cosm + CO_K + swaddr(0, seg * 16 + i2, az * 2)));
            zw[(seg * 16 + i2) * 64 + az] = run;
        }
    }
    __syncthreads();

    {
        const int tx = tid & 15, ty = tid >> 4;
        const float* nm = (const float*)(cosm + CO_NUM);
        const float* zw = (const float*)(cosm + CO_ZW);
        #pragma unroll
        for (int ii = 0; ii < 4; ii++) {
            const int i = ty * 4 + ii;
            float4 n4 = *(const float4*)(nm + i * 72 + tx * 4);
            float4 z4 = *(const float4*)(zw + i * 64 + tx * 4);
            unsigned short o[4];
            #pragma unroll
            for (int aa = 0; aa < 4; aa++) {
                const int a = tx * 4 + aa;
                const float qv = __half2float(
                    *(const __half*)(cosm + CO_Q + swaddr(0, i, a * 2)));
                o[aa] = __half_as_ushort(
                    __float2half_rn((&n4.x)[aa] / (qv * (&z4.x)[aa] + EPSC)));
            }
            uint2 u;
            u.x = (uint32_t)o[0] | ((uint32_t)o[1] << 16);
            u.y = (uint32_t)o[2] | ((uint32_t)o[3] << 16);
            *(uint2*)(O16 + base + (size_t)i * DM + tx * 4) = u;
        }
    }
}

// ---------------------------------------------------------------------------
// kernel_launch — 5 launches, sequential.
// ---------------------------------------------------------------------------
extern "C" void kernel_launch(void* const* d_in, const int* in_sizes, int n_in,
                              void* d_out, int out_size)
{
    const float* queries = (const float*)d_in[0];
    const float* keys    = (const float*)d_in[1];
    const float* values  = (const float*)d_in[2];
    const float* Wq = (const float*)d_in[3];
    const float* bq = (const float*)d_in[4];
    const float* Wk = (const float*)d_in[5];
    const float* bk = (const float*)d_in[6];
    const float* Wv = (const float*)d_in[7];
    const float* bv = (const float*)d_in[8];
    const float* Wo = (const float*)d_in[9];
    const float* bo = (const float*)d_in[10];
    float* out = (float*)d_out;

    float *pS, *pZ;
    __half *pA16, *pW16, *pQ16, *pK16, *pV16;
    cudaGetSymbolAddress((void**)&pS, g_S);
    cudaGetSymbolAddress((void**)&pZ, g_Z);
    cudaGetSymbolAddress((void**)&pA16, g_A16);
    cudaGetSymbolAddress((void**)&pW16, g_W16);
    cudaGetSymbolAddress((void**)&pQ16, g_Q16);
    cudaGetSymbolAddress((void**)&pK16, g_K16);
    cudaGetSymbolAddress((void**)&pV16, g_V16);

    cudaFuncSetAttribute(gemm_tc_kernel,
                         cudaFuncAttributeMaxDynamicSharedMemorySize, SMEM_GEMM);
    cudaFuncSetAttribute(attn_chunk_out,
                         cudaFuncAttributeMaxDynamicSharedMemorySize, CO_SMEM);

    const dim3 chunk_grid(NCH, B_ * H_);

    // 1) all converts in one launch (3 input slabs + 4 weight slabs)
    conv_all<<<3 * CONVA_BLOCKS + 4096, 256>>>(queries, keys, values,
                                               Wq, Wk, Wv, Wo, pA16, pW16);
    // 2) projections -> fp16 Q,K,V (act on q,k)
    gemm_tc_kernel<<<dim3(DM / 128, M_ / 128, 3), 256, SMEM_GEMM>>>(
        pA16, pW16, bq, bk, bv, pQ16, pK16, pV16, 0b011, 1);
    // 3) fused chunk sums + exclusive prefix (persistent per-(b,h) CTAs, 8 warps)
    attn_sums_prefix<<<B_ * H_, 256>>>(pK16, pV16, pS, pZ);
    // 4) per-chunk outputs -> fp16 A16 slab 0
    attn_chunk_out<<<chunk_grid, 256, CO_SMEM>>>(pQ16, pK16, pV16, pS, pZ, pA16);
    // 5) output projection (W slab 3), fp32 out
    gemm_tc_kernel<<<dim3(DM / 128, M_ / 128, 1), 256, SMEM_GEMM>>>(
        pA16, pW16 + (size_t)3 * DM * DM, bo, bo, bo, out, out, out, 0, 0);
}

// round 17
// speedup vs baseline: 1.1835x; 1.0421x over previous
#include <cuda_runtime.h>
#include <cuda_fp16.h>
#include <cstdint>
#include <math.h>

// Problem constants
#define B_   4
#define L_   2048
#define DM   1024
#define H_   16
#define HD   64
#define M_   (B_ * L_)       // 8192 rows
#define EPSC 1e-6f
#define CH   64              // scan chunk length
#define NCH  (L_ / CH)       // 32 chunks

// GEMM constants (validated shape): CTA 128x128, warp tile 32x64, BK=64
#define KC        64
#define KCHUNKS   (DM / KC)           // 16
#define TILE_B    16384               // 128-row x 128-byte tile
#define STG_B     (2 * TILE_B)        // 32 KB
#define NSTG      3
#define SMEM_GEMM (NSTG * STG_B)      // 96 KB, occ 2

// chunk_out dynamic smem layout (bytes)
#define CO_Q    0
#define CO_V    8192
#define CO_K    16384
#define CO_SP   24576
#define CO_NUM  32768                       // float [64][72]
#define CO_ZW   (CO_NUM + 64 * 72 * 4)      // 51200: float [64][64]
#define CO_RED  (CO_ZW + 64 * 64 * 4)       // 67584: float [2][16][68]
#define CO_PART (CO_RED + 2 * 16 * 68 * 4)  // 76288: float [4][64]
#define CO_SMEM (CO_PART + 4 * 64 * 4)      // 77312

#define CONVA_BLOCKS (M_ * DM / 1024)       // 8192 blocks per input slab

// ---------------------------------------------------------------------------
// Scratch (allocation-free rule: __device__ globals)
// ---------------------------------------------------------------------------
__device__ __half g_S16[(size_t)B_ * H_ * NCH * HD * HD]; // excl-prefix S, fp16 swizzled
__device__ float  g_Z[(size_t)B_ * H_ * NCH * HD];        // excl-prefix Z
__device__ __half g_A16[(size_t)3 * M_ * DM];             // fp16 A slabs (in / attn out)
__device__ __half g_W16[(size_t)4 * DM * DM];             // [N,K] fp16, 4 slabs
__device__ __half g_Q16[(size_t)M_ * DM];
__device__ __half g_K16[(size_t)M_ * DM];
__device__ __half g_V16[(size_t)M_ * DM];

// ---------------------------------------------------------------------------
// PTX helpers (base-target sm_103-safe)
// ---------------------------------------------------------------------------
__device__ __forceinline__ uint32_t smem_u32(const void* p) {
    uint32_t a;
    asm("{ .reg .u64 t; cvta.to.shared.u64 t, %1; cvt.u32.u64 %0, t; }" : "=r"(a) : "l"(p));
    return a;
}
__device__ __forceinline__ void cp16(uint32_t saddr, const void* g) {
    asm volatile("cp.async.cg.shared.global [%0], [%1], 16;\n" :: "r"(saddr), "l"(g));
}
#define CP_COMMIT() asm volatile("cp.async.commit_group;\n")
#define CP_WAIT0()  asm volatile("cp.async.wait_group 0;\n")
#define CP_WAIT1()  asm volatile("cp.async.wait_group 1;\n")

__device__ __forceinline__ void ldsm4(uint32_t* r, uint32_t addr) {
    asm volatile("ldmatrix.sync.aligned.m8n8.x4.shared.b16 {%0,%1,%2,%3}, [%4];"
                 : "=r"(r[0]), "=r"(r[1]), "=r"(r[2]), "=r"(r[3]) : "r"(addr));
}
__device__ __forceinline__ void ldsm4t(uint32_t* r, uint32_t addr) {
    asm volatile("ldmatrix.sync.aligned.m8n8.x4.trans.shared.b16 {%0,%1,%2,%3}, [%4];"
                 : "=r"(r[0]), "=r"(r[1]), "=r"(r[2]), "=r"(r[3]) : "r"(addr));
}
__device__ __forceinline__ void mma16816(float* d, const uint32_t* a,
                                         uint32_t b0, uint32_t b1) {
    asm volatile(
        "mma.sync.aligned.m16n8k16.row.col.f32.f16.f16.f32 "
        "{%0,%1,%2,%3}, {%4,%5,%6,%7}, {%8,%9}, {%0,%1,%2,%3};"
        : "+f"(d[0]), "+f"(d[1]), "+f"(d[2]), "+f"(d[3])
        : "r"(a[0]), "r"(a[1]), "r"(a[2]), "r"(a[3]), "r"(b0), "r"(b1));
}
__device__ __forceinline__ uint32_t pack2(float lo, float hi) {
    uint32_t d;
    asm("cvt.rn.f16x2.f32 %0, %1, %2;" : "=r"(d) : "f"(hi), "f"(lo));
    return d;
}

// SW128 swizzle within a tile of 128-byte rows
__device__ __forceinline__ uint32_t swaddr(uint32_t tilebase, int row, int cbyte) {
    uint32_t off = ((uint32_t)(row >> 3) << 10) + ((uint32_t)(row & 7) << 7)
                 + (uint32_t)cbyte;
    return tilebase + (off ^ ((off >> 3) & 0x70u));
}
// Fragment source address: row-major operand [r][k]
__device__ __forceinline__ uint32_t naddr(uint32_t tile, int r0, int kb, int q, int lr) {
    return swaddr(tile, r0 + (q & 1) * 8 + lr, kb + (q >> 1) * 16);
}
// Trans fragment: smem holds T[j][col]; want op[m_or_n=col][k=j]
__device__ __forceinline__ uint32_t taddr(uint32_t tile, int j0, int col0, int q, int lr) {
    return swaddr(tile, j0 + (q >> 1) * 8 + lr, (col0 + (q & 1) * 8) * 2);
}

// ---------------------------------------------------------------------------
// Merged converter: one launch covers 3 input slabs + 4 weight slabs.
// ---------------------------------------------------------------------------
__global__ __launch_bounds__(256)
void conv_all(const float* __restrict__ X0, const float* __restrict__ X1,
              const float* __restrict__ X2,
              const float* __restrict__ W0, const float* __restrict__ W1,
              const float* __restrict__ W2, const float* __restrict__ W3,
              __half* __restrict__ YA, __half* __restrict__ YW)
{
    __shared__ float s[32][33];
    const int bid = blockIdx.x;
    if (bid < 3 * CONVA_BLOCKS) {
        const int slab = bid / CONVA_BLOCKS;
        const int ib   = bid - slab * CONVA_BLOCKS;
        const float* X = (slab == 0) ? X0 : (slab == 1) ? X1 : X2;
        const size_t i = ((size_t)ib * 256 + threadIdx.x) * 4;
        float4 v = *(const float4*)(X + i);
        uint2 u;
        u.x = pack2(v.x, v.y);
        u.y = pack2(v.z, v.w);
        *(uint2*)(YA + (size_t)slab * M_ * DM + i) = u;
    } else {
        const int wb   = bid - 3 * CONVA_BLOCKS;      // 0..4095
        const int slab = wb >> 10;
        const int rem  = wb & 1023;
        const float* W = (slab == 0) ? W0 : (slab == 1) ? W1
                         : (slab == 2) ? W2 : W3;
        __half* Yo = YW + (size_t)slab * DM * DM;
        const int n0 = (rem & 31) * 32, k0 = (rem >> 5) * 32;
        const int tx = threadIdx.x & 31, ty = threadIdx.x >> 5;
        #pragma unroll
        for (int i = 0; i < 4; i++)
            s[ty + i * 8][tx] = W[(size_t)(k0 + ty + i * 8) * DM + n0 + tx];
        __syncthreads();
        #pragma unroll
        for (int i = 0; i < 4; i++) {
            float x = s[tx][ty + i * 8];
            Yo[(size_t)(n0 + ty + i * 8) * DM + k0 + tx] = __float2half_rn(x);
        }
    }
}

// ---------------------------------------------------------------------------
// fp16 tensor GEMM (validated R12/R13), fp32 or fp16 output, slab-batched.
// ---------------------------------------------------------------------------
__device__ __forceinline__ void load_chunk(
    const __half* A16, const __half* B16,
    size_t aRowBase, int n0, int tid, int ch, uint32_t stg)
{
    const int r0 = tid >> 3;
    const int c  = tid & 7;
    const uint32_t kbyte = (uint32_t)ch * (KC * 2);
    #pragma unroll
    for (int i = 0; i < 4; i++) {
        const int r = r0 + 32 * i;
        const uint32_t sw = swaddr(0, r, c * 16);
        cp16(stg + 0 * TILE_B + sw,
             (const char*)A16 + (aRowBase + r) * (DM * 2) + kbyte + c * 16);
        cp16(stg + 1 * TILE_B + sw,
             (const char*)B16 + (size_t)(n0 + r) * (DM * 2) + kbyte + c * 16);
    }
}

__global__ __launch_bounds__(256, 2)
void gemm_tc_kernel(const __half* __restrict__ A16,
                    const __half* __restrict__ W16,
                    const float* __restrict__ b0, const float* __restrict__ b1,
                    const float* __restrict__ b2,
                    void* C0v, void* C1v, void* C2v,
                    int actmask, int outhalf)
{
    extern __shared__ char smem[];
    const uint32_t sbase = smem_u32(smem);

    const int slab = blockIdx.z;
    const __half* B16 = W16 + (size_t)slab * DM * DM;
    const float* bias = (slab == 0) ? b0 : (slab == 1) ? b1 : b2;
    void* Cv = (slab == 0) ? C0v : (slab == 1) ? C1v : C2v;
    const int act = (actmask >> slab) & 1;

    const int tid  = threadIdx.x;
    const int wid  = tid >> 5, lane = tid & 31;
    const int wr   = wid & 3;
    const int wc   = wid >> 2;
    const int m0 = blockIdx.y * 128;
    const size_t aRowBase = (size_t)slab * M_ + m0;
    const int n0 = blockIdx.x * 128;

    const int q   = lane >> 3;
    const int lr  = lane & 7;
    const int kQ  = (q >> 1) * 16;

    float acc[2][8][4];
    #pragma unroll
    for (int mt = 0; mt < 2; mt++)
        #pragma unroll
        for (int nt = 0; nt < 8; nt++)
            #pragma unroll
            for (int e = 0; e < 4; e++) acc[mt][nt][e] = 0.f;

    load_chunk(A16, B16, aRowBase, n0, tid, 0, sbase + 0 * STG_B);
    CP_COMMIT();
    load_chunk(A16, B16, aRowBase, n0, tid, 1, sbase + 1 * STG_B);
    CP_COMMIT();

    for (int chk = 0; chk < KCHUNKS; chk++) {
        CP_WAIT1();
        __syncthreads();

        if (chk + 2 < KCHUNKS)
            load_chunk(A16, B16, aRowBase, n0, tid, chk + 2,
                       sbase + ((chk + 2) % NSTG) * STG_B);
        CP_COMMIT();

        const uint32_t stg = sbase + (chk % NSTG) * STG_B;
        const uint32_t tA  = stg + 0 * TILE_B;
        const uint32_t tB  = stg + 1 * TILE_B;

        #pragma unroll
        for (int k16 = 0; k16 < 4; k16++) {
            const int kb = k16 * 32 + kQ;
            uint32_t Af[2][4];
            #pragma unroll
            for (int mt = 0; mt < 2; mt++)
                ldsm4(Af[mt], swaddr(tA, wr * 32 + mt * 16 + (q & 1) * 8 + lr, kb));
            #pragma unroll
            for (int g = 0; g < 4; g++) {
                uint32_t Bf[4];
                ldsm4(Bf, swaddr(tB, wc * 64 + g * 16 + (q & 1) * 8 + lr, kb));
                #pragma unroll
                for (int s = 0; s < 2; s++) {
                    const int nt = g * 2 + s;
                    #pragma unroll
                    for (int mt = 0; mt < 2; mt++)
                        mma16816(acc[mt][nt], Af[mt], Bf[s], Bf[s + 2]);
                }
            }
        }
    }

    // epilogue
    #pragma unroll
    for (int mt = 0; mt < 2; mt++) {
        const int row = m0 + wr * 32 + mt * 16 + (lane >> 2);
        #pragma unroll
        for (int nt = 0; nt < 8; nt++) {
            const int col = n0 + wc * 64 + nt * 8 + 2 * (lane & 3);
            const float bb0 = bias[col], bb1 = bias[col + 1];
            float v0 = acc[mt][nt][0] + bb0;
            float v1 = acc[mt][nt][1] + bb1;
            float v2 = acc[mt][nt][2] + bb0;
            float v3 = acc[mt][nt][3] + bb1;
            if (act) {
                v0 = (v0 > 0.f) ? (v0 + 1.f) : expf(v0);
                v1 = (v1 > 0.f) ? (v1 + 1.f) : expf(v1);
                v2 = (v2 > 0.f) ? (v2 + 1.f) : expf(v2);
                v3 = (v3 > 0.f) ? (v3 + 1.f) : expf(v3);
            }
            if (outhalf) {
                __half* Ch = (__half*)Cv;
                *(uint32_t*)(Ch + (size_t)row * DM + col)       = pack2(v0, v1);
                *(uint32_t*)(Ch + (size_t)(row + 8) * DM + col) = pack2(v2, v3);
            } else {
                float* C = (float*)Cv;
                *(float2*)(C + (size_t)row * DM + col)       = make_float2(v0, v1);
                *(float2*)(C + (size_t)(row + 8) * DM + col) = make_float2(v2, v3);
            }
        }
    }
}

// ---------------------------------------------------------------------------
// Fused scan head: per (b,h) persistent CTA, 256 threads, 8 warps (warp tile
// 16c x 32a). Accumulator BEFORE adding chunk ch == exclusive prefix -> packed
// to fp16 and stored PRE-SWIZZLED (exact tile layout chunk_out consumes).
// ---------------------------------------------------------------------------
__global__ __launch_bounds__(256, 1)
void attn_sums_prefix(const __half* __restrict__ K16,
                      const __half* __restrict__ V16,
                      __half* __restrict__ S16,
                      float* __restrict__ Z)
{
    __shared__ __align__(128) __half sK[2][64 * 64];
    __shared__ __align__(128) __half sV[2][64 * 64];
    __shared__ float sZp[4][64];

    const int bh = blockIdx.x;
    const int b = bh >> 4, h = bh & 15;
    const size_t hbase = (size_t)b * L_ * DM + h * HD;
    const int tid = threadIdx.x;
    const uint32_t uK0 = smem_u32(sK[0]), uV0 = smem_u32(sV[0]);

    const int wid = tid >> 5, lane = tid & 31;
    const int q = lane >> 3, lr = lane & 7;
    const int c0 = (wid >> 1) * 16;   // 4 c-tiles of 16
    const int a0 = (wid & 1) * 32;    // 2 a-tiles of 32

    float sacc[4][4];
    #pragma unroll
    for (int nt = 0; nt < 4; nt++)
        #pragma unroll
        for (int e = 0; e < 4; e++) sacc[nt][e] = 0.f;
    float zrun = 0.f;

    for (int f = tid; f < 512; f += 256) {
        const int r = f >> 3, c = f & 7;
        const uint32_t sw = swaddr(0, r, c * 16);
        cp16(uK0 + sw, K16 + hbase + (size_t)r * DM + c * 8);
        cp16(uV0 + sw, V16 + hbase + (size_t)r * DM + c * 8);
    }
    CP_COMMIT();

    for (int ch = 0; ch < NCH; ch++) {
        CP_WAIT0();
        __syncthreads();

        if (ch + 1 < NCH) {
            const int nb = (ch + 1) & 1;
            const uint32_t uKn = smem_u32(sK[nb]), uVn = smem_u32(sV[nb]);
            const size_t base = hbase + (size_t)(ch + 1) * CH * DM;
            for (int f = tid; f < 512; f += 256) {
                const int r = f >> 3, c = f & 7;
                const uint32_t sw = swaddr(0, r, c * 16);
                cp16(uKn + sw, K16 + base + (size_t)r * DM + c * 8);
                cp16(uVn + sw, V16 + base + (size_t)r * DM + c * 8);
            }
        }
        CP_COMMIT();

        // store exclusive prefix for chunk ch: fp16, swizzled tile
        {
            char* sout = (char*)(S16 + ((size_t)bh * NCH + ch) * (HD * HD));
            #pragma unroll
            for (int nt = 0; nt < 4; nt++) {
                const int c = c0 + (lane >> 2);
                const int a = a0 + nt * 8 + 2 * (lane & 3);
                *(uint32_t*)(sout + swaddr(0, c,     a * 2)) =
                    pack2(sacc[nt][0], sacc[nt][1]);
                *(uint32_t*)(sout + swaddr(0, c + 8, a * 2)) =
                    pack2(sacc[nt][2], sacc[nt][3]);
            }
            if (tid < 64)
                Z[((size_t)bh * NCH + ch) * HD + tid] = zrun;
        }

        const int buf = ch & 1;
        const uint32_t uK = smem_u32(sK[buf]), uV = smem_u32(sV[buf]);

        // Z chunk partials: 4 segments of 16 rows per column
        {
            const int col = tid & 63, seg = tid >> 6;
            float s16 = 0.f;
            #pragma unroll
            for (int i = 0; i < 16; i++)
                s16 += __half2float(
                    *(const __half*)((const char*)sK[buf] +
                                     swaddr(0, seg * 16 + i, col * 2)));
            sZp[seg][col] = s16;
        }

        // mma-accumulate chunk ch: S[c][a] += sum_j V[j][c] K[j][a]
        #pragma unroll
        for (int jk = 0; jk < 4; jk++) {
            uint32_t Af[4];
            ldsm4t(Af, taddr(uV, jk * 16, c0, q, lr));
            #pragma unroll
            for (int nb = 0; nb < 2; nb++) {
                uint32_t Bf[4];
                ldsm4t(Bf, taddr(uK, jk * 16, a0 + nb * 16, q, lr));
                mma16816(sacc[nb * 2 + 0], Af, Bf[0], Bf[2]);
                mma16816(sacc[nb * 2 + 1], Af, Bf[1], Bf[3]);
            }
        }

        __syncthreads();
        if (tid < 64)
            zrun += sZp[0][tid] + sZp[1][tid] + sZp[2][tid] + sZp[3][tid];
    }
}

// ---------------------------------------------------------------------------
// Scan kernel C: per-chunk outputs, tensorized. Sp now fp16 pre-swizzled:
// all four input tiles stream via one cp.async batch.
// ---------------------------------------------------------------------------
__global__ __launch_bounds__(256, 2)
void attn_chunk_out(const __half* __restrict__ Q16,
                    const __half* __restrict__ K16,
                    const __half* __restrict__ V16,
                    const __half* __restrict__ S16,
                    const float* __restrict__ Zp,
                    __half* __restrict__ O16)
{
    extern __shared__ char cosm[];
    const uint32_t ub = smem_u32(cosm);

    const int ch = blockIdx.x, bh = blockIdx.y;
    const int b = bh >> 4, h = bh & 15;
    const size_t base = ((size_t)(b * L_ + ch * CH)) * DM + h * HD;
    const int tid = threadIdx.x;

    {
        const char* spTile =
            (const char*)(S16 + ((size_t)bh * NCH + ch) * (HD * HD));
        for (int f = tid; f < 512; f += 256) {
            const int r = f >> 3, c = f & 7;
            const uint32_t sw = swaddr(0, r, c * 16);
            cp16(ub + CO_Q + sw, Q16 + base + (size_t)r * DM + c * 8);
            cp16(ub + CO_V + sw, V16 + base + (size_t)r * DM + c * 8);
            cp16(ub + CO_K + sw, K16 + base + (size_t)r * DM + c * 8);
            cp16(ub + CO_SP + sw, spTile + sw);
        }
    }
    CP_COMMIT();
    CP_WAIT0();
    __syncthreads();

    const int wid = tid >> 5, lane = tid & 31;
    const int q = lane >> 3, lr = lane & 7;
    const int wr = wid & 3, wc = wid >> 2;
    const int i0 = wr * 16, j0 = wc * 32;
    const bool active = (j0 <= i0 + 15);

    const uint32_t uQ = ub + CO_Q, uV = ub + CO_V, uK = ub + CO_K, uSp = ub + CO_SP;

    float numacc[8][4];
    #pragma unroll
    for (int nt = 0; nt < 8; nt++)
        #pragma unroll
        for (int e = 0; e < 4; e++) numacc[nt][e] = 0.f;

    if (active) {
        float gacc[4][4];
        #pragma unroll
        for (int nt = 0; nt < 4; nt++)
            #pragma unroll
            for (int e = 0; e < 4; e++) gacc[nt][e] = 0.f;

        #pragma unroll
        for (int kc = 0; kc < 4; kc++) {
            const int kb = kc * 32 + (q >> 1) * 16;
            uint32_t Aq[4];
            ldsm4(Aq, naddr(uQ, i0, kc * 32, q, lr));
            #pragma unroll
            for (int g = 0; g < 2; g++) {
                uint32_t Bv[4];
                ldsm4(Bv, swaddr(uV, j0 + g * 16 + (q & 1) * 8 + lr, kb));
                mma16816(gacc[g * 2 + 0], Aq, Bv[0], Bv[2]);
                mma16816(gacc[g * 2 + 1], Aq, Bv[1], Bv[3]);
            }
            if (wc == 0) {
                #pragma unroll
                for (int nb = 0; nb < 4; nb++) {
                    uint32_t Bs[4];
                    ldsm4t(Bs, taddr(uSp, kc * 16, nb * 16, q, lr));
                    mma16816(numacc[nb * 2 + 0], Aq, Bs[0], Bs[2]);
                    mma16816(numacc[nb * 2 + 1], Aq, Bs[1], Bs[3]);
                }
            }
        }

        #pragma unroll
        for (int nt = 0; nt < 4; nt++) {
            const int jb = j0 + nt * 8 + 2 * (lane & 3);
            const int ib = i0 + (lane >> 2);
            if (jb     > ib)     gacc[nt][0] = 0.f;
            if (jb + 1 > ib)     gacc[nt][1] = 0.f;
            if (jb     > ib + 8) gacc[nt][2] = 0.f;
            if (jb + 1 > ib + 8) gacc[nt][3] = 0.f;
        }
        uint32_t aG[2][4];
        #pragma unroll
        for (int t = 0; t < 2; t++) {
            aG[t][0] = pack2(gacc[2 * t][0],     gacc[2 * t][1]);
            aG[t][1] = pack2(gacc[2 * t][2],     gacc[2 * t][3]);
            aG[t][2] = pack2(gacc[2 * t + 1][0], gacc[2 * t + 1][1]);
            aG[t][3] = pack2(gacc[2 * t + 1][2], gacc[2 * t + 1][3]);
        }
        #pragma unroll
        for (int t = 0; t < 2; t++)
            #pragma unroll
            for (int nb = 0; nb < 4; nb++) {
                uint32_t Bk[4];
                ldsm4t(Bk, taddr(uK, j0 + t * 16, nb * 16, q, lr));
                mma16816(numacc[nb * 2 + 0], aG[t], Bk[0], Bk[2]);
                mma16816(numacc[nb * 2 + 1], aG[t], Bk[1], Bk[3]);
            }
    }

    if (wc == 1 && wr >= 2) {
        float* red = (float*)(cosm + CO_RED) + (size_t)(wr - 2) * 16 * 68;
        #pragma unroll
        for (int nt = 0; nt < 8; nt++) {
            const int r = lane >> 2, a = nt * 8 + 2 * (lane & 3);
            *(float2*)(red + r * 68 + a)       = make_float2(numacc[nt][0], numacc[nt][1]);
            *(float2*)(red + (r + 8) * 68 + a) = make_float2(numacc[nt][2], numacc[nt][3]);
        }
    }
    __syncthreads();

    if (wc == 0) {
        if (wr >= 2) {
            const float* red = (const float*)(cosm + CO_RED) + (size_t)(wr - 2) * 16 * 68;
            #pragma unroll
            for (int nt = 0; nt < 8; nt++) {
                const int r = lane >> 2, a = nt * 8 + 2 * (lane & 3);
                float2 p0 = *(const float2*)(red + r * 68 + a);
                float2 p1 = *(const float2*)(red + (r + 8) * 68 + a);
                numacc[nt][0] += p0.x; numacc[nt][1] += p0.y;
                numacc[nt][2] += p1.x; numacc[nt][3] += p1.y;
            }
        }
        float* nm = (float*)(cosm + CO_NUM);
        #pragma unroll
        for (int nt = 0; nt < 8; nt++) {
            const int r = wr * 16 + (lane >> 2), a = nt * 8 + 2 * (lane & 3);
            *(float2*)(nm + r * 72 + a)       = make_float2(numacc[nt][0], numacc[nt][1]);
            *(float2*)(nm + (r + 8) * 72 + a) = make_float2(numacc[nt][2], numacc[nt][3]);
        }
    }
    __syncthreads();

    {
        const int az = tid & 63, seg = tid >> 6;
        float s16 = 0.f;
        #pragma unroll
        for (int i2 = 0; i2 < 16; i2++)
            s16 += __half2float(*(const __half*)(cosm + CO_K + swaddr(0, seg * 16 + i2, az * 2)));
        float* part = (float*)(cosm + CO_PART);
        part[seg * 64 + az] = s16;
        __syncthreads();
        float run = Zp[((size_t)bh * NCH + ch) * HD + az];
        #pragma unroll
        for (int s2 = 0; s2 < 3; s2++)
            if (s2 < seg) run += part[s2 * 64 + az];
        float* zw = (float*)(cosm + CO_ZW);
        #pragma unroll
        for (int i2 = 0; i2 < 16; i2++) {
            run += __half2float(*(const __half*)(cosm + CO_K + swaddr(0, seg * 16 + i2, az * 2)));
            zw[(seg * 16 + i2) * 64 + az] = run;
        }
    }
    __syncthreads();

    {
        const int tx = tid & 15, ty = tid >> 4;
        const float* nm = (const float*)(cosm + CO_NUM);
        const float* zw = (const float*)(cosm + CO_ZW);
        #pragma unroll
        for (int ii = 0; ii < 4; ii++) {
            const int i = ty * 4 + ii;
            float4 n4 = *(const float4*)(nm + i * 72 + tx * 4);
            float4 z4 = *(const float4*)(zw + i * 64 + tx * 4);
            unsigned short o[4];
            #pragma unroll
            for (int aa = 0; aa < 4; aa++) {
                const int a = tx * 4 + aa;
                const float qv = __half2float(
                    *(const __half*)(cosm + CO_Q + swaddr(0, i, a * 2)));
                o[aa] = __half_as_ushort(
                    __float2half_rn((&n4.x)[aa] / (qv * (&z4.x)[aa] + EPSC)));
            }
            uint2 u;
            u.x = (uint32_t)o[0] | ((uint32_t)o[1] << 16);
            u.y = (uint32_t)o[2] | ((uint32_t)o[3] << 16);
            *(uint2*)(O16 + base + (size_t)i * DM + tx * 4) = u;
        }
    }
}

// ---------------------------------------------------------------------------
// kernel_launch — 5 launches, sequential.
// ---------------------------------------------------------------------------
extern "C" void kernel_launch(void* const* d_in, const int* in_sizes, int n_in,
                              void* d_out, int out_size)
{
    const float* queries = (const float*)d_in[0];
    const float* keys    = (const float*)d_in[1];
    const float* values  = (const float*)d_in[2];
    const float* Wq = (const float*)d_in[3];
    const float* bq = (const float*)d_in[4];
    const float* Wk = (const float*)d_in[5];
    const float* bk = (const float*)d_in[6];
    const float* Wv = (const float*)d_in[7];
    const float* bv = (const float*)d_in[8];
    const float* Wo = (const float*)d_in[9];
    const float* bo = (const float*)d_in[10];
    float* out = (float*)d_out;

    float *pZ;
    __half *pS16, *pA16, *pW16, *pQ16, *pK16, *pV16;
    cudaGetSymbolAddress((void**)&pS16, g_S16);
    cudaGetSymbolAddress((void**)&pZ, g_Z);
    cudaGetSymbolAddress((void**)&pA16, g_A16);
    cudaGetSymbolAddress((void**)&pW16, g_W16);
    cudaGetSymbolAddress((void**)&pQ16, g_Q16);
    cudaGetSymbolAddress((void**)&pK16, g_K16);
    cudaGetSymbolAddress((void**)&pV16, g_V16);

    cudaFuncSetAttribute(gemm_tc_kernel,
                         cudaFuncAttributeMaxDynamicSharedMemorySize, SMEM_GEMM);
    cudaFuncSetAttribute(attn_chunk_out,
                         cudaFuncAttributeMaxDynamicSharedMemorySize, CO_SMEM);

    const dim3 chunk_grid(NCH, B_ * H_);

    // 1) all converts in one launch (3 input slabs + 4 weight slabs)
    conv_all<<<3 * CONVA_BLOCKS + 4096, 256>>>(queries, keys, values,
                                               Wq, Wk, Wv, Wo, pA16, pW16);
    // 2) projections -> fp16 Q,K,V (act on q,k)
    gemm_tc_kernel<<<dim3(DM / 128, M_ / 128, 3), 256, SMEM_GEMM>>>(
        pA16, pW16, bq, bk, bv, pQ16, pK16, pV16, 0b011, 1);
    // 3) fused chunk sums + exclusive prefix -> fp16 swizzled S tiles
    attn_sums_prefix<<<B_ * H_, 256>>>(pK16, pV16, pS16, pZ);
    // 4) per-chunk outputs -> fp16 A16 slab 0
    attn_chunk_out<<<chunk_grid, 256, CO_SMEM>>>(pQ16, pK16, pV16, pS16, pZ, pA16);
    // 5) output projection (W slab 3), fp32 out
    gemm_tc_kernel<<<dim3(DM / 128, M_ / 128, 1), 256, SMEM_GEMM>>>(
        pA16, pW16 + (size_t)3 * DM * DM, bo, bo, bo, out, out, out, 0, 0);
}